// round 1
// baseline (speedup 1.0000x reference)
#include <cuda_runtime.h>
#include <cstring>

#define K_CODES 1024
#define DIM 64
#define N_PTS 131072
#define GAMMA_F 0.99f
#define ONE_M_GAMMA 0.01f
#define ALPHA_F 1e-9f
#define BETA_F 0.25f
#define CHUNK 128

// ---- scratch (no allocations allowed) ----
__device__ float g_esq[K_CODES];
__device__ float g_counts[K_CODES];
__device__ float g_sums[K_CODES * DIM];
__device__ int   g_amin[N_PTS];
__device__ float g_loss;

// packed fp32x2 FMA (sm_103a; ptxas will not auto-fuse — PTX only)
__device__ __forceinline__ void fma2(unsigned long long &d,
                                     unsigned long long a,
                                     unsigned long long b) {
    asm("fma.rn.f32x2 %0, %1, %2, %0;" : "+l"(d) : "l"(a), "l"(b));
}

__device__ __forceinline__ float2 u2f(unsigned long long v) {
    float2 f; memcpy(&f, &v, 8); return f;
}

// ---------------------------------------------------------------------------
// Kernel 1: zero scratch + E squared norms
// ---------------------------------------------------------------------------
__global__ void init_kernel(const float* __restrict__ E) {
    int tid = blockIdx.x * blockDim.x + threadIdx.x;
    if (tid < K_CODES * DIM) g_sums[tid] = 0.0f;
    if (tid < K_CODES) {
        const float4* er = (const float4*)(E + (size_t)tid * DIM);
        float s = 0.0f;
        #pragma unroll
        for (int j = 0; j < 16; j++) {
            float4 v = er[j];
            s += v.x * v.x + v.y * v.y + v.z * v.z + v.w * v.w;
        }
        g_esq[tid] = s;
        g_counts[tid] = 0.0f;
    }
    if (tid == 0) g_loss = 0.0f;
}

// ---------------------------------------------------------------------------
// Kernel 2: distances + argmin + scatter stats
// 1 point per thread; X row in packed f32x2 registers; E chunked via smem.
// ---------------------------------------------------------------------------
__global__ void __launch_bounds__(256, 2)
dist_kernel(const float* __restrict__ X, const float* __restrict__ E,
            float* __restrict__ out_arg, float* __restrict__ out_mind) {
    __shared__ float se[CHUNK * DIM];     // 32 KB
    __shared__ float sesq[CHUNK];
    __shared__ float sred[256];

    const int pt = blockIdx.x * 256 + threadIdx.x;

    // load X row as 32 packed f32x2 values
    unsigned long long x2[32];
    {
        const ulonglong2* xr = (const ulonglong2*)(X + (size_t)pt * DIM);
        #pragma unroll
        for (int j = 0; j < 16; j++) {
            ulonglong2 v = xr[j];
            x2[2 * j]     = v.x;
            x2[2 * j + 1] = v.y;
        }
    }
    float xsq = 0.0f;
    #pragma unroll
    for (int j = 0; j < 32; j++) {
        float2 f = u2f(x2[j]);
        xsq += f.x * f.x + f.y * f.y;
    }

    float best = 3.4e38f;
    int bidx = 0;

    for (int c0 = 0; c0 < K_CODES; c0 += CHUNK) {
        __syncthreads();
        {
            const float4* src = (const float4*)(E + (size_t)c0 * DIM);
            float4* dst = (float4*)se;
            #pragma unroll
            for (int i = threadIdx.x; i < CHUNK * DIM / 4; i += 256)
                dst[i] = src[i];
            if (threadIdx.x < CHUNK) sesq[threadIdx.x] = g_esq[c0 + threadIdx.x];
        }
        __syncthreads();

        const ulonglong2* se2 = (const ulonglong2*)se;
        for (int c = 0; c < CHUNK; c++) {
            const ulonglong2* er = se2 + c * 16;
            unsigned long long a0 = 0, a1 = 0, a2 = 0, a3 = 0;
            #pragma unroll
            for (int j = 0; j < 16; j += 2) {
                ulonglong2 e0 = er[j];
                ulonglong2 e1 = er[j + 1];
                fma2(a0, x2[2 * j],     e0.x);
                fma2(a1, x2[2 * j + 1], e0.y);
                fma2(a2, x2[2 * j + 2], e1.x);
                fma2(a3, x2[2 * j + 3], e1.y);
            }
            float2 f0 = u2f(a0), f1 = u2f(a1), f2 = u2f(a2), f3 = u2f(a3);
            float dot = ((f0.x + f0.y) + (f1.x + f1.y)) +
                        ((f2.x + f2.y) + (f3.x + f3.y));
            float dist = xsq + sesq[c] - 2.0f * dot;
            if (dist < best) { best = dist; bidx = c0 + c; }  // strict <: first-min
        }
    }

    out_arg[pt]  = (float)bidx;
    out_mind[pt] = best;
    g_amin[pt]   = bidx;

    atomicAdd(&g_counts[bidx], 1.0f);

    // segment-sum of X rows via vector reductions (no return value needed)
    float* sp = &g_sums[(size_t)bidx * DIM];
    #pragma unroll
    for (int j = 0; j < 16; j++) {
        float2 lo = u2f(x2[2 * j]);
        float2 hi = u2f(x2[2 * j + 1]);
        asm volatile("red.global.add.v4.f32 [%0], {%1,%2,%3,%4};"
                     :: "l"(sp + 4 * j), "f"(lo.x), "f"(lo.y), "f"(hi.x), "f"(hi.y)
                     : "memory");
    }

    // loss partial: sum of min_dist over block
    sred[threadIdx.x] = best;
    __syncthreads();
    for (int s = 128; s > 0; s >>= 1) {
        if (threadIdx.x < s) sred[threadIdx.x] += sred[threadIdx.x + s];
        __syncthreads();
    }
    if (threadIdx.x == 0) atomicAdd(&g_loss, sred[0]);
}

// ---------------------------------------------------------------------------
// Kernel 3: Z_embs = E[argmin]  (straight-through output == gathered codes)
// ---------------------------------------------------------------------------
__global__ void gather_kernel(const float* __restrict__ E, float4* __restrict__ z) {
    int idx = blockIdx.x * 256 + threadIdx.x;   // N*16 float4 elements
    int row = idx >> 4;
    int d   = idx & 15;
    z[idx] = ((const float4*)E)[(size_t)g_amin[row] * 16 + d];
}

// ---------------------------------------------------------------------------
// Kernel 4: EMA finalize (cs, ma, E_new) + loss
// ---------------------------------------------------------------------------
__global__ void finalize_kernel(const float* __restrict__ cluster_sizes,
                                const float* __restrict__ moving_avg,
                                float* __restrict__ out_loss,
                                float* __restrict__ out_enew,
                                float* __restrict__ out_cs,
                                float* __restrict__ out_ma) {
    __shared__ float sred[1024];
    __shared__ float s_total;
    int k = threadIdx.x;

    float cs_pre = GAMMA_F * cluster_sizes[k] + ONE_M_GAMMA * g_counts[k];
    sred[k] = cs_pre;
    __syncthreads();
    for (int s = 512; s > 0; s >>= 1) {
        if (k < s) sred[k] += sred[k + s];
        __syncthreads();
    }
    if (k == 0) s_total = sred[0];
    __syncthreads();

    float denom = 1.0f + ALPHA_F * (float)K_CODES / s_total;
    float cs = (cs_pre + ALPHA_F) / denom;
    out_cs[k] = cs;

    for (int d = 0; d < DIM; d++) {
        int i = k * DIM + d;
        float ma = GAMMA_F * moving_avg[i] + ONE_M_GAMMA * g_sums[i];
        out_ma[i]   = ma;
        out_enew[i] = ma / cs;
    }
    if (k == 0) out_loss[0] = BETA_F * g_loss / (float)N_PTS;
}

// ---------------------------------------------------------------------------
// launch
// ---------------------------------------------------------------------------
extern "C" void kernel_launch(void* const* d_in, const int* in_sizes, int n_in,
                              void* d_out, int out_size) {
    const float* X    = (const float*)d_in[0];
    const float* E    = (const float*)d_in[1];
    const float* cssz = (const float*)d_in[2];
    const float* mavg = (const float*)d_in[3];

    float* out = (float*)d_out;
    // layout: Z_embs[N,D] | loss | argmins[N] | min_dist[N] | E_new[K,D] | cs[K] | ma[K,D]
    float* out_z    = out;
    float* out_loss = out + (size_t)N_PTS * DIM;
    float* out_arg  = out_loss + 1;
    float* out_mind = out_arg + N_PTS;
    float* out_enew = out_mind + N_PTS;
    float* out_cs   = out_enew + K_CODES * DIM;
    float* out_ma   = out_cs + K_CODES;

    init_kernel<<<(K_CODES * DIM) / 256, 256>>>(E);
    dist_kernel<<<N_PTS / 256, 256>>>(X, E, out_arg, out_mind);
    gather_kernel<<<(N_PTS * 16) / 256, 256>>>(E, (float4*)out_z);
    finalize_kernel<<<1, 1024>>>(cssz, mavg, out_loss, out_enew, out_cs, out_ma);
}

// round 2
// speedup vs baseline: 1.3066x; 1.3066x over previous
#include <cuda_runtime.h>
#include <cstring>

#define K_CODES 1024
#define DIM 64
#define N_PTS 131072
#define GAMMA_F 0.99f
#define ONE_M_GAMMA 0.01f
#define ALPHA_F 1e-9f
#define BETA_F 0.25f
#define CHUNK 128

// ---- scratch (no allocations allowed) ----
__device__ float g_esq[K_CODES];
__device__ float g_counts[K_CODES];
__device__ float g_sums[K_CODES * DIM];
__device__ int   g_amin[N_PTS];
__device__ float g_loss;
__device__ float g_cs_inv[K_CODES];

// packed fp32x2 ops (sm_103a; PTX-only, ptxas won't auto-fuse)
__device__ __forceinline__ void fma2(unsigned long long &d,
                                     unsigned long long a,
                                     unsigned long long b) {
    asm("fma.rn.f32x2 %0, %1, %2, %0;" : "+l"(d) : "l"(a), "l"(b));
}
__device__ __forceinline__ void add2(unsigned long long &d,
                                     unsigned long long a) {
    asm("add.rn.f32x2 %0, %0, %1;" : "+l"(d) : "l"(a));
}
__device__ __forceinline__ float2 u2f(unsigned long long v) {
    float2 f; memcpy(&f, &v, 8); return f;
}

// ---------------------------------------------------------------------------
// Kernel 1: zero scratch + E squared norms
// ---------------------------------------------------------------------------
__global__ void init_kernel(const float* __restrict__ E) {
    int tid = blockIdx.x * blockDim.x + threadIdx.x;
    if (tid < K_CODES * DIM) g_sums[tid] = 0.0f;
    if (tid < K_CODES) {
        const float4* er = (const float4*)(E + (size_t)tid * DIM);
        float s = 0.0f;
        #pragma unroll
        for (int j = 0; j < 16; j++) {
            float4 v = er[j];
            s += v.x * v.x + v.y * v.y + v.z * v.z + v.w * v.w;
        }
        g_esq[tid] = s;
        g_counts[tid] = 0.0f;
    }
    if (tid == 0) g_loss = 0.0f;
}

// ---------------------------------------------------------------------------
// Kernel 2: distances + argmin + scatter stats
// 1 point per thread; X row in packed f32x2 registers; E chunked via smem.
// Comparison key = esq - 2*dot (xsq is a per-thread constant: order-preserving).
// ---------------------------------------------------------------------------
__global__ void __launch_bounds__(256, 2)
dist_kernel(const float* __restrict__ X, const float* __restrict__ E,
            float* __restrict__ out_arg, float* __restrict__ out_mind) {
    __shared__ float se[CHUNK * DIM];     // 32 KB
    __shared__ float sesq[CHUNK];
    __shared__ float sred[256];

    const int pt = blockIdx.x * 256 + threadIdx.x;

    // load X row as 32 packed f32x2 values
    unsigned long long x2[32];
    {
        const ulonglong2* xr = (const ulonglong2*)(X + (size_t)pt * DIM);
        #pragma unroll
        for (int j = 0; j < 16; j++) {
            ulonglong2 v = xr[j];
            x2[2 * j]     = v.x;
            x2[2 * j + 1] = v.y;
        }
    }
    float xsq = 0.0f;
    #pragma unroll
    for (int j = 0; j < 32; j++) {
        float2 f = u2f(x2[j]);
        xsq += f.x * f.x + f.y * f.y;
    }

    float best = 3.4e38f;   // best key = esq - 2*dot
    int bidx = 0;

    for (int c0 = 0; c0 < K_CODES; c0 += CHUNK) {
        __syncthreads();
        {
            const float4* src = (const float4*)(E + (size_t)c0 * DIM);
            float4* dst = (float4*)se;
            #pragma unroll
            for (int i = threadIdx.x; i < CHUNK * DIM / 4; i += 256)
                dst[i] = src[i];
            if (threadIdx.x < CHUNK) sesq[threadIdx.x] = g_esq[c0 + threadIdx.x];
        }
        __syncthreads();

        const ulonglong2* se2 = (const ulonglong2*)se;
        for (int c = 0; c < CHUNK; c++) {
            const ulonglong2* er = se2 + c * 16;
            unsigned long long a0 = 0, a1 = 0, a2 = 0, a3 = 0;
            #pragma unroll
            for (int j = 0; j < 16; j += 2) {
                ulonglong2 e0 = er[j];
                ulonglong2 e1 = er[j + 1];
                fma2(a0, x2[2 * j],     e0.x);
                fma2(a1, x2[2 * j + 1], e0.y);
                fma2(a2, x2[2 * j + 2], e1.x);
                fma2(a3, x2[2 * j + 3], e1.y);
            }
            add2(a0, a1);
            add2(a2, a3);
            add2(a0, a2);
            float2 f0 = u2f(a0);
            float dot = f0.x + f0.y;
            float key = fmaf(-2.0f, dot, sesq[c]);
            if (key < best) { best = key; bidx = c0 + c; }  // strict <: first-min
        }
    }

    float mind = xsq + best;
    out_arg[pt]  = (float)bidx;
    out_mind[pt] = mind;
    g_amin[pt]   = bidx;

    atomicAdd(&g_counts[bidx], 1.0f);

    // segment-sum of X rows via vector reductions (no return value needed)
    float* sp = &g_sums[(size_t)bidx * DIM];
    #pragma unroll
    for (int j = 0; j < 16; j++) {
        float2 lo = u2f(x2[2 * j]);
        float2 hi = u2f(x2[2 * j + 1]);
        asm volatile("red.global.add.v4.f32 [%0], {%1,%2,%3,%4};"
                     :: "l"(sp + 4 * j), "f"(lo.x), "f"(lo.y), "f"(hi.x), "f"(hi.y)
                     : "memory");
    }

    // loss partial: sum of min_dist over block
    sred[threadIdx.x] = mind;
    __syncthreads();
    for (int s = 128; s > 0; s >>= 1) {
        if (threadIdx.x < s) sred[threadIdx.x] += sred[threadIdx.x + s];
        __syncthreads();
    }
    if (threadIdx.x == 0) atomicAdd(&g_loss, sred[0]);
}

// ---------------------------------------------------------------------------
// Kernel 3: Z_embs = E[argmin]
// ---------------------------------------------------------------------------
__global__ void gather_kernel(const float* __restrict__ E, float4* __restrict__ z) {
    int idx = blockIdx.x * 256 + threadIdx.x;   // N*16 float4 elements
    int row = idx >> 4;
    int d   = idx & 15;
    z[idx] = ((const float4*)E)[(size_t)g_amin[row] * 16 + d];
}

// ---------------------------------------------------------------------------
// Kernel 4a: cs + loss (1 block over K)
// ---------------------------------------------------------------------------
__global__ void cs_kernel(const float* __restrict__ cluster_sizes,
                          float* __restrict__ out_loss,
                          float* __restrict__ out_cs) {
    __shared__ float warp_sums[32];
    int k = threadIdx.x;

    float cs_pre = GAMMA_F * cluster_sizes[k] + ONE_M_GAMMA * g_counts[k];

    // block-wide sum via shuffles
    float v = cs_pre;
    #pragma unroll
    for (int o = 16; o > 0; o >>= 1)
        v += __shfl_xor_sync(0xffffffffu, v, o);
    if ((k & 31) == 0) warp_sums[k >> 5] = v;
    __syncthreads();
    if (k < 32) {
        float w = warp_sums[k];
        #pragma unroll
        for (int o = 16; o > 0; o >>= 1)
            w += __shfl_xor_sync(0xffffffffu, w, o);
        if (k == 0) warp_sums[0] = w;
    }
    __syncthreads();
    float total = warp_sums[0];

    float denom = 1.0f + ALPHA_F * (float)K_CODES / total;
    float cs = (cs_pre + ALPHA_F) / denom;
    out_cs[k]   = cs;
    g_cs_inv[k] = 1.0f / cs;

    if (k == 0) out_loss[0] = BETA_F * g_loss / (float)N_PTS;
}

// ---------------------------------------------------------------------------
// Kernel 4b: ma + E_new (grid-wide over K*D)
// ---------------------------------------------------------------------------
__global__ void ema_kernel(const float* __restrict__ moving_avg,
                           float* __restrict__ out_enew,
                           float* __restrict__ out_ma) {
    int i = blockIdx.x * 256 + threadIdx.x;   // K*DIM elements
    int k = i >> 6;
    float ma = GAMMA_F * moving_avg[i] + ONE_M_GAMMA * g_sums[i];
    out_ma[i]   = ma;
    out_enew[i] = ma * g_cs_inv[k];
}

// ---------------------------------------------------------------------------
// launch
// ---------------------------------------------------------------------------
extern "C" void kernel_launch(void* const* d_in, const int* in_sizes, int n_in,
                              void* d_out, int out_size) {
    const float* X    = (const float*)d_in[0];
    const float* E    = (const float*)d_in[1];
    const float* cssz = (const float*)d_in[2];
    const float* mavg = (const float*)d_in[3];

    float* out = (float*)d_out;
    // layout: Z_embs[N,D] | loss | argmins[N] | min_dist[N] | E_new[K,D] | cs[K] | ma[K,D]
    float* out_z    = out;
    float* out_loss = out + (size_t)N_PTS * DIM;
    float* out_arg  = out_loss + 1;
    float* out_mind = out_arg + N_PTS;
    float* out_enew = out_mind + N_PTS;
    float* out_cs   = out_enew + K_CODES * DIM;
    float* out_ma   = out_cs + K_CODES;

    init_kernel<<<(K_CODES * DIM) / 256, 256>>>(E);
    dist_kernel<<<N_PTS / 256, 256>>>(X, E, out_arg, out_mind);
    gather_kernel<<<(N_PTS * 16) / 256, 256>>>(E, (float4*)out_z);
    cs_kernel<<<1, 1024>>>(cssz, out_loss, out_cs);
    ema_kernel<<<(K_CODES * DIM) / 256, 256>>>(mavg, out_enew, out_ma);
}

// round 3
// speedup vs baseline: 1.6346x; 1.2510x over previous
#include <cuda_runtime.h>
#include <cstring>

#define K_CODES 1024
#define DIM 64
#define N_PTS 131072
#define GAMMA_F 0.99f
#define ONE_M_GAMMA 0.01f
#define ALPHA_F 1e-9f
#define BETA_F 0.25f
#define CHUNK 128

// ---- scratch (no allocations allowed) ----
__device__ float g_esq[K_CODES];
__device__ float g_counts[K_CODES];
__device__ float g_sums[K_CODES * DIM];
__device__ int   g_amin[N_PTS];
__device__ float g_loss;
__device__ float g_cs_inv[K_CODES];

// packed fp32x2 ops (sm_103a; PTX-only, ptxas won't auto-fuse)
__device__ __forceinline__ void fma2(unsigned long long &d,
                                     unsigned long long a,
                                     unsigned long long b) {
    asm("fma.rn.f32x2 %0, %1, %2, %0;" : "+l"(d) : "l"(a), "l"(b));
}
__device__ __forceinline__ void add2(unsigned long long &d,
                                     unsigned long long a) {
    asm("add.rn.f32x2 %0, %0, %1;" : "+l"(d) : "l"(a));
}
__device__ __forceinline__ float2 u2f(unsigned long long v) {
    float2 f; memcpy(&f, &v, 8); return f;
}

// ---------------------------------------------------------------------------
// Kernel 1: zero scratch + E squared norms
// ---------------------------------------------------------------------------
__global__ void init_kernel(const float* __restrict__ E) {
    int tid = blockIdx.x * blockDim.x + threadIdx.x;
    if (tid < K_CODES * DIM) g_sums[tid] = 0.0f;
    if (tid < K_CODES) {
        const float4* er = (const float4*)(E + (size_t)tid * DIM);
        float s = 0.0f;
        #pragma unroll
        for (int j = 0; j < 16; j++) {
            float4 v = er[j];
            s += v.x * v.x + v.y * v.y + v.z * v.z + v.w * v.w;
        }
        g_esq[tid] = s;
        g_counts[tid] = 0.0f;
    }
    if (tid == 0) g_loss = 0.0f;
}

// ---------------------------------------------------------------------------
// Kernel 2: distances + argmin + scatter stats.
// 2 points per thread (register-blocked) so each E LDS.128 feeds 4 fma2.
// Comparison key = esq - 2*dot (xsq per-point constant: order-preserving).
// ---------------------------------------------------------------------------
__global__ void __launch_bounds__(128, 3)
dist_kernel(const float* __restrict__ X, const float* __restrict__ E,
            float* __restrict__ out_arg, float* __restrict__ out_mind) {
    __shared__ float se[CHUNK * DIM];     // 32 KB
    __shared__ float sesq[CHUNK];
    __shared__ float sred[128];

    const int base = blockIdx.x * 256;
    const int ptA  = base + threadIdx.x;
    const int ptB  = base + 128 + threadIdx.x;

    // load both X rows as packed f32x2 values
    unsigned long long xA[32], xB[32];
    {
        const ulonglong2* xr = (const ulonglong2*)(X + (size_t)ptA * DIM);
        #pragma unroll
        for (int j = 0; j < 16; j++) {
            ulonglong2 v = xr[j];
            xA[2 * j] = v.x; xA[2 * j + 1] = v.y;
        }
        xr = (const ulonglong2*)(X + (size_t)ptB * DIM);
        #pragma unroll
        for (int j = 0; j < 16; j++) {
            ulonglong2 v = xr[j];
            xB[2 * j] = v.x; xB[2 * j + 1] = v.y;
        }
    }
    float xsqA = 0.0f, xsqB = 0.0f;
    #pragma unroll
    for (int j = 0; j < 32; j++) {
        float2 fa = u2f(xA[j]); xsqA += fa.x * fa.x + fa.y * fa.y;
        float2 fb = u2f(xB[j]); xsqB += fb.x * fb.x + fb.y * fb.y;
    }

    float bestA = 3.4e38f, bestB = 3.4e38f;
    int bidxA = 0, bidxB = 0;

    for (int c0 = 0; c0 < K_CODES; c0 += CHUNK) {
        __syncthreads();
        {
            const float4* src = (const float4*)(E + (size_t)c0 * DIM);
            float4* dst = (float4*)se;
            #pragma unroll
            for (int i = threadIdx.x; i < CHUNK * DIM / 4; i += 128)
                dst[i] = src[i];
            if (threadIdx.x < CHUNK) sesq[threadIdx.x] = g_esq[c0 + threadIdx.x];
        }
        __syncthreads();

        const ulonglong2* se2 = (const ulonglong2*)se;
        for (int c = 0; c < CHUNK; c++) {
            const ulonglong2* er = se2 + c * 16;
            unsigned long long a0 = 0, a1 = 0, b0 = 0, b1 = 0;
            #pragma unroll
            for (int j = 0; j < 16; j++) {
                ulonglong2 e = er[j];
                fma2(a0, xA[2 * j],     e.x);
                fma2(a1, xA[2 * j + 1], e.y);
                fma2(b0, xB[2 * j],     e.x);
                fma2(b1, xB[2 * j + 1], e.y);
            }
            float eq = sesq[c];
            add2(a0, a1);
            add2(b0, b1);
            float2 fa = u2f(a0), fb = u2f(b0);
            float keyA = fmaf(-2.0f, fa.x + fa.y, eq);
            float keyB = fmaf(-2.0f, fb.x + fb.y, eq);
            if (keyA < bestA) { bestA = keyA; bidxA = c0 + c; }  // strict <: first-min
            if (keyB < bestB) { bestB = keyB; bidxB = c0 + c; }
        }
    }

    float mindA = xsqA + bestA;
    float mindB = xsqB + bestB;

    out_arg[ptA]  = (float)bidxA;
    out_arg[ptB]  = (float)bidxB;
    out_mind[ptA] = mindA;
    out_mind[ptB] = mindB;
    g_amin[ptA]   = bidxA;
    g_amin[ptB]   = bidxB;

    atomicAdd(&g_counts[bidxA], 1.0f);
    atomicAdd(&g_counts[bidxB], 1.0f);

    // segment-sum of X rows via vector reductions
    float* spA = &g_sums[(size_t)bidxA * DIM];
    float* spB = &g_sums[(size_t)bidxB * DIM];
    #pragma unroll
    for (int j = 0; j < 16; j++) {
        float2 lo = u2f(xA[2 * j]);
        float2 hi = u2f(xA[2 * j + 1]);
        asm volatile("red.global.add.v4.f32 [%0], {%1,%2,%3,%4};"
                     :: "l"(spA + 4 * j), "f"(lo.x), "f"(lo.y), "f"(hi.x), "f"(hi.y)
                     : "memory");
        lo = u2f(xB[2 * j]);
        hi = u2f(xB[2 * j + 1]);
        asm volatile("red.global.add.v4.f32 [%0], {%1,%2,%3,%4};"
                     :: "l"(spB + 4 * j), "f"(lo.x), "f"(lo.y), "f"(hi.x), "f"(hi.y)
                     : "memory");
    }

    // loss partial: sum of both min_dists over block
    sred[threadIdx.x] = mindA + mindB;
    __syncthreads();
    for (int s = 64; s > 0; s >>= 1) {
        if (threadIdx.x < s) sred[threadIdx.x] += sred[threadIdx.x + s];
        __syncthreads();
    }
    if (threadIdx.x == 0) atomicAdd(&g_loss, sred[0]);
}

// ---------------------------------------------------------------------------
// Kernel 3: Z_embs = E[argmin]
// ---------------------------------------------------------------------------
__global__ void gather_kernel(const float* __restrict__ E, float4* __restrict__ z) {
    int idx = blockIdx.x * 256 + threadIdx.x;   // N*16 float4 elements
    int row = idx >> 4;
    int d   = idx & 15;
    z[idx] = ((const float4*)E)[(size_t)g_amin[row] * 16 + d];
}

// ---------------------------------------------------------------------------
// Kernel 4a: cs + loss (1 block over K)
// ---------------------------------------------------------------------------
__global__ void cs_kernel(const float* __restrict__ cluster_sizes,
                          float* __restrict__ out_loss,
                          float* __restrict__ out_cs) {
    __shared__ float warp_sums[32];
    int k = threadIdx.x;

    float cs_pre = GAMMA_F * cluster_sizes[k] + ONE_M_GAMMA * g_counts[k];

    float v = cs_pre;
    #pragma unroll
    for (int o = 16; o > 0; o >>= 1)
        v += __shfl_xor_sync(0xffffffffu, v, o);
    if ((k & 31) == 0) warp_sums[k >> 5] = v;
    __syncthreads();
    if (k < 32) {
        float w = warp_sums[k];
        #pragma unroll
        for (int o = 16; o > 0; o >>= 1)
            w += __shfl_xor_sync(0xffffffffu, w, o);
        if (k == 0) warp_sums[0] = w;
    }
    __syncthreads();
    float total = warp_sums[0];

    float denom = 1.0f + ALPHA_F * (float)K_CODES / total;
    float cs = (cs_pre + ALPHA_F) / denom;
    out_cs[k]   = cs;
    g_cs_inv[k] = 1.0f / cs;

    if (k == 0) out_loss[0] = BETA_F * g_loss / (float)N_PTS;
}

// ---------------------------------------------------------------------------
// Kernel 4b: ma + E_new (grid-wide over K*D)
// ---------------------------------------------------------------------------
__global__ void ema_kernel(const float* __restrict__ moving_avg,
                           float* __restrict__ out_enew,
                           float* __restrict__ out_ma) {
    int i = blockIdx.x * 256 + threadIdx.x;   // K*DIM elements
    int k = i >> 6;
    float ma = GAMMA_F * moving_avg[i] + ONE_M_GAMMA * g_sums[i];
    out_ma[i]   = ma;
    out_enew[i] = ma * g_cs_inv[k];
}

// ---------------------------------------------------------------------------
// launch
// ---------------------------------------------------------------------------
extern "C" void kernel_launch(void* const* d_in, const int* in_sizes, int n_in,
                              void* d_out, int out_size) {
    const float* X    = (const float*)d_in[0];
    const float* E    = (const float*)d_in[1];
    const float* cssz = (const float*)d_in[2];
    const float* mavg = (const float*)d_in[3];

    float* out = (float*)d_out;
    // layout: Z_embs[N,D] | loss | argmins[N] | min_dist[N] | E_new[K,D] | cs[K] | ma[K,D]
    float* out_z    = out;
    float* out_loss = out + (size_t)N_PTS * DIM;
    float* out_arg  = out_loss + 1;
    float* out_mind = out_arg + N_PTS;
    float* out_enew = out_mind + N_PTS;
    float* out_cs   = out_enew + K_CODES * DIM;
    float* out_ma   = out_cs + K_CODES;

    init_kernel<<<(K_CODES * DIM) / 256, 256>>>(E);
    dist_kernel<<<N_PTS / 256, 128>>>(X, E, out_arg, out_mind);
    gather_kernel<<<(N_PTS * 16) / 256, 256>>>(E, (float4*)out_z);
    cs_kernel<<<1, 1024>>>(cssz, out_loss, out_cs);
    ema_kernel<<<(K_CODES * DIM) / 256, 256>>>(mavg, out_enew, out_ma);
}

// round 6
// speedup vs baseline: 2.4313x; 1.4874x over previous
#include <cuda_runtime.h>
#include <cuda_bf16.h>
#include <cstdint>

#define K_CODES 1024
#define DIM 64
#define N_PTS 131072
#define GAMMA_F 0.99f
#define ONE_M_GAMMA 0.01f
#define ALPHA_F 1e-9f
#define BETA_F 0.25f

#define CCHUNK 128              // codes per smem chunk
#define ROW_PITCH 144           // bytes per code row in smem (64*2 + 16 pad)
#define SPLIT_STRIDE (CCHUNK * ROW_PITCH)   // 18432
#define SM_B 0
#define SM_ESQ (3 * SPLIT_STRIDE)           // 55296
#define SM_RED (SM_ESQ + CCHUNK * 4)        // 55808
#define SM_TOTAL (SM_RED + 256 * 4)         // 56832

// ---- scratch (__device__ globals; no allocs) ----
__device__ __align__(16) __nv_bfloat16 g_Xs0[N_PTS * DIM];
__device__ __align__(16) __nv_bfloat16 g_Xs1[N_PTS * DIM];
__device__ __align__(16) __nv_bfloat16 g_Xs2[N_PTS * DIM];
__device__ __align__(16) __nv_bfloat16 g_Es0[K_CODES * DIM];
__device__ __align__(16) __nv_bfloat16 g_Es1[K_CODES * DIM];
__device__ __align__(16) __nv_bfloat16 g_Es2[K_CODES * DIM];
__device__ __align__(16) float g_esq[K_CODES];
__device__ float g_xsq[N_PTS];
__device__ float g_counts[K_CODES];
__device__ float g_sums[K_CODES * DIM];
__device__ int   g_amin[N_PTS];
__device__ float g_loss;
__device__ float g_cs_inv[K_CODES];

// mma.sync m16n8k16 bf16 (sm_80+ baseline; valid at compute_103)
#define MMA16816(d, a, b0v, b1v, c)                                          \
    asm volatile("mma.sync.aligned.m16n8k16.row.col.f32.bf16.bf16.f32 "      \
        "{%0,%1,%2,%3}, {%4,%5,%6,%7}, {%8,%9}, {%10,%11,%12,%13};"          \
        : "=f"((d)[0]), "=f"((d)[1]), "=f"((d)[2]), "=f"((d)[3])             \
        : "r"((a)[0]), "r"((a)[1]), "r"((a)[2]), "r"((a)[3]),                \
          "r"(b0v), "r"(b1v),                                                \
          "f"((c)[0]), "f"((c)[1]), "f"((c)[2]), "f"((c)[3]))

// ---------------------------------------------------------------------------
// prep_E: 3-term bf16 splits of e + esq.  grid = K*DIM/256, block 256.
// ---------------------------------------------------------------------------
__global__ void prep_E(const float* __restrict__ E) {
    __shared__ float ws[8];
    int e = blockIdx.x * 256 + threadIdx.x;
    float v = E[e];

    __nv_bfloat16 h0 = __float2bfloat16(v);
    float r1 = v - __bfloat162float(h0);
    __nv_bfloat16 h1 = __float2bfloat16(r1);
    float r2 = r1 - __bfloat162float(h1);
    __nv_bfloat16 h2 = __float2bfloat16(r2);
    g_Es0[e] = h0; g_Es1[e] = h1; g_Es2[e] = h2;

    float sq = v * v;
    #pragma unroll
    for (int o = 16; o > 0; o >>= 1) sq += __shfl_xor_sync(0xffffffffu, sq, o);
    if ((threadIdx.x & 31) == 0) ws[threadIdx.x >> 5] = sq;
    __syncthreads();
    if ((threadIdx.x & 63) == 0) {
        int g = threadIdx.x >> 6;
        g_esq[e >> 6] = ws[2 * g] + ws[2 * g + 1];
    }
}

// ---------------------------------------------------------------------------
// prep_X: 3-term bf16 splits of (-2x) + xsq.  grid = N*DIM/256.
// ---------------------------------------------------------------------------
__global__ void prep_X(const float* __restrict__ X) {
    __shared__ float ws[8];
    int e = blockIdx.x * 256 + threadIdx.x;
    float x = X[e];
    float y = -2.0f * x;

    __nv_bfloat16 h0 = __float2bfloat16(y);
    float r1 = y - __bfloat162float(h0);
    __nv_bfloat16 h1 = __float2bfloat16(r1);
    float r2 = r1 - __bfloat162float(h1);
    __nv_bfloat16 h2 = __float2bfloat16(r2);
    g_Xs0[e] = h0; g_Xs1[e] = h1; g_Xs2[e] = h2;

    float sq = x * x;
    #pragma unroll
    for (int o = 16; o > 0; o >>= 1) sq += __shfl_xor_sync(0xffffffffu, sq, o);
    if ((threadIdx.x & 31) == 0) ws[threadIdx.x >> 5] = sq;
    __syncthreads();
    if ((threadIdx.x & 63) == 0) {
        int g = threadIdx.x >> 6;
        g_xsq[e >> 6] = ws[2 * g] + ws[2 * g + 1];
    }
}

__global__ void zero_stats() {
    int i = blockIdx.x * 256 + threadIdx.x;
    g_sums[i] = 0.0f;
    if (i < K_CODES) g_counts[i] = 0.0f;
    if (i == 0) g_loss = 0.0f;
}

// ---------------------------------------------------------------------------
// dist kernel: HMMA bf16 3-split, key = esq - 2*x.e, argmin + stats.
// 256 threads = 8 warps x 16 points = 128 points/CTA. grid = N/128.
// ---------------------------------------------------------------------------
__global__ void __launch_bounds__(256, 2)
dist_kernel(const float* __restrict__ X,
            float* __restrict__ out_arg, float* __restrict__ out_mind) {
    extern __shared__ char smem[];
    const int tid = threadIdx.x;
    const int wid = tid >> 5;
    const int lane = tid & 31;
    const int g = lane >> 2;          // 0..7
    const int q = lane & 3;           // 0..3
    const int tileRow = blockIdx.x * 128 + wid * 16;
    const int row0 = tileRow + g;
    const int row1 = row0 + 8;

    // ---- A fragments: 3 splits x 4 kchunks x 4 regs, resident all loop ----
    unsigned A[3][4][4];
    {
        const __nv_bfloat16* xs[3] = {g_Xs0, g_Xs1, g_Xs2};
        #pragma unroll
        for (int s = 0; s < 3; s++) {
            #pragma unroll
            for (int kc = 0; kc < 4; kc++) {
                size_t b0 = (size_t)row0 * DIM + kc * 16 + q * 2;
                size_t b1 = (size_t)row1 * DIM + kc * 16 + q * 2;
                A[s][kc][0] = *(const unsigned*)(xs[s] + b0);
                A[s][kc][1] = *(const unsigned*)(xs[s] + b1);
                A[s][kc][2] = *(const unsigned*)(xs[s] + b0 + 8);
                A[s][kc][3] = *(const unsigned*)(xs[s] + b1 + 8);
            }
        }
    }

    float zero4[4] = {0.0f, 0.0f, 0.0f, 0.0f};
    float best0 = 3.4e38f, best1 = 3.4e38f;
    int idx0 = 0, idx1 = 0;

    for (int chunk = 0; chunk < K_CODES / CCHUNK; chunk++) {
        __syncthreads();
        // stage B chunk (3 splits, 128 codes, 144B pitch) + esq
        {
            const __nv_bfloat16* es[3] = {g_Es0, g_Es1, g_Es2};
            for (int i = tid; i < 3 * CCHUNK * 8; i += 256) {
                int s = i >> 10;
                int r = i & 1023;
                int n = r >> 3, c = r & 7;
                const uint4* src = (const uint4*)(es[s] + (size_t)chunk * CCHUNK * DIM);
                *(uint4*)(smem + SM_B + s * SPLIT_STRIDE + n * ROW_PITCH + c * 16) = src[r];
            }
            if (tid < CCHUNK / 4)
                ((uint4*)(smem + SM_ESQ))[tid] =
                    ((const uint4*)(g_esq + chunk * CCHUNK))[tid];
        }
        __syncthreads();

        #pragma unroll 2
        for (int nb = 0; nb < CCHUNK / 8; nb++) {
            const int nloc = nb * 8 + g;
            const char* bbase = smem + SM_B + nloc * ROW_PITCH + q * 4;
            float cacc[4][4];

            #pragma unroll
            for (int kc = 0; kc < 4; kc++) {
                const char* bk = bbase + kc * 32;
                unsigned b00 = *(const unsigned*)(bk);
                unsigned b01 = *(const unsigned*)(bk + 16);
                unsigned b10 = *(const unsigned*)(bk + SPLIT_STRIDE);
                unsigned b11 = *(const unsigned*)(bk + SPLIT_STRIDE + 16);
                unsigned b20 = *(const unsigned*)(bk + 2 * SPLIT_STRIDE);
                unsigned b21 = *(const unsigned*)(bk + 2 * SPLIT_STRIDE + 16);
                MMA16816(cacc[kc], A[0][kc], b00, b01, zero4);   // x0*e0
                MMA16816(cacc[kc], A[0][kc], b10, b11, cacc[kc]); // x0*e1
                MMA16816(cacc[kc], A[1][kc], b00, b01, cacc[kc]); // x1*e0
                MMA16816(cacc[kc], A[0][kc], b20, b21, cacc[kc]); // x0*e2
                MMA16816(cacc[kc], A[1][kc], b10, b11, cacc[kc]); // x1*e1
                MMA16816(cacc[kc], A[2][kc], b00, b01, cacc[kc]); // x2*e0
            }

            float2 eq = *(const float2*)(smem + SM_ESQ + (nb * 8 + 2 * q) * 4);
            float k0 = ((cacc[0][0] + cacc[1][0]) + (cacc[2][0] + cacc[3][0])) + eq.x;
            float k1 = ((cacc[0][1] + cacc[1][1]) + (cacc[2][1] + cacc[3][1])) + eq.y;
            float k2 = ((cacc[0][2] + cacc[1][2]) + (cacc[2][2] + cacc[3][2])) + eq.x;
            float k3 = ((cacc[0][3] + cacc[1][3]) + (cacc[2][3] + cacc[3][3])) + eq.y;

            int col = chunk * CCHUNK + nb * 8 + 2 * q;
            if (k0 < best0) { best0 = k0; idx0 = col; }        // ascending: first-min
            if (k1 < best0) { best0 = k1; idx0 = col + 1; }
            if (k2 < best1) { best1 = k2; idx1 = col; }
            if (k3 < best1) { best1 = k3; idx1 = col + 1; }
        }
    }

    // ---- combine across the 4 quad lanes (cols), tie -> lower index ----
    #pragma unroll
    for (int o = 1; o < 4; o <<= 1) {
        float ob = __shfl_xor_sync(0xffffffffu, best0, o);
        int   oi = __shfl_xor_sync(0xffffffffu, idx0,  o);
        if (ob < best0 || (ob == best0 && oi < idx0)) { best0 = ob; idx0 = oi; }
        ob = __shfl_xor_sync(0xffffffffu, best1, o);
        oi = __shfl_xor_sync(0xffffffffu, idx1,  o);
        if (ob < best1 || (ob == best1 && oi < idx1)) { best1 = ob; idx1 = oi; }
    }

    float lsum = 0.0f;
    if (q == 0) {
        float m0 = g_xsq[row0] + best0;
        float m1 = g_xsq[row1] + best1;
        out_arg[row0]  = (float)idx0;  out_arg[row1]  = (float)idx1;
        out_mind[row0] = m0;           out_mind[row1] = m1;
        g_amin[row0]   = idx0;         g_amin[row1]   = idx1;
        atomicAdd(&g_counts[idx0], 1.0f);
        atomicAdd(&g_counts[idx1], 1.0f);
        lsum = m0 + m1;

        const float4* xr0 = (const float4*)(X + (size_t)row0 * DIM);
        const float4* xr1 = (const float4*)(X + (size_t)row1 * DIM);
        float* sp0 = &g_sums[(size_t)idx0 * DIM];
        float* sp1 = &g_sums[(size_t)idx1 * DIM];
        #pragma unroll
        for (int j = 0; j < 16; j++) {
            float4 v = xr0[j];
            asm volatile("red.global.add.v4.f32 [%0], {%1,%2,%3,%4};"
                         :: "l"(sp0 + 4 * j), "f"(v.x), "f"(v.y), "f"(v.z), "f"(v.w)
                         : "memory");
            v = xr1[j];
            asm volatile("red.global.add.v4.f32 [%0], {%1,%2,%3,%4};"
                         :: "l"(sp1 + 4 * j), "f"(v.x), "f"(v.y), "f"(v.z), "f"(v.w)
                         : "memory");
        }
    }

    float* sred = (float*)(smem + SM_RED);
    __syncthreads();   // B-stage area done; sred region distinct anyway
    sred[tid] = lsum;
    __syncthreads();
    for (int s = 128; s > 0; s >>= 1) {
        if (tid < s) sred[tid] += sred[tid + s];
        __syncthreads();
    }
    if (tid == 0) atomicAdd(&g_loss, sred[0]);
}

// ---------------------------------------------------------------------------
// gather: Z_embs = E[argmin]
// ---------------------------------------------------------------------------
__global__ void gather_kernel(const float* __restrict__ E, float4* __restrict__ z) {
    int idx = blockIdx.x * 256 + threadIdx.x;
    int row = idx >> 4;
    int d   = idx & 15;
    z[idx] = ((const float4*)E)[(size_t)g_amin[row] * 16 + d];
}

// ---------------------------------------------------------------------------
// cs + loss
// ---------------------------------------------------------------------------
__global__ void cs_kernel(const float* __restrict__ cluster_sizes,
                          float* __restrict__ out_loss, float* __restrict__ out_cs) {
    __shared__ float warp_sums[32];
    int k = threadIdx.x;
    float cs_pre = GAMMA_F * cluster_sizes[k] + ONE_M_GAMMA * g_counts[k];
    float v = cs_pre;
    #pragma unroll
    for (int o = 16; o > 0; o >>= 1) v += __shfl_xor_sync(0xffffffffu, v, o);
    if ((k & 31) == 0) warp_sums[k >> 5] = v;
    __syncthreads();
    if (k < 32) {
        float w = warp_sums[k];
        #pragma unroll
        for (int o = 16; o > 0; o >>= 1) w += __shfl_xor_sync(0xffffffffu, w, o);
        if (k == 0) warp_sums[0] = w;
    }
    __syncthreads();
    float total = warp_sums[0];
    float denom = 1.0f + ALPHA_F * (float)K_CODES / total;
    float cs = (cs_pre + ALPHA_F) / denom;
    out_cs[k]   = cs;
    g_cs_inv[k] = 1.0f / cs;
    if (k == 0) out_loss[0] = BETA_F * g_loss / (float)N_PTS;
}

// ---------------------------------------------------------------------------
// ma + E_new
// ---------------------------------------------------------------------------
__global__ void ema_kernel(const float* __restrict__ moving_avg,
                           float* __restrict__ out_enew, float* __restrict__ out_ma) {
    int i = blockIdx.x * 256 + threadIdx.x;
    int k = i >> 6;
    float ma = GAMMA_F * moving_avg[i] + ONE_M_GAMMA * g_sums[i];
    out_ma[i]   = ma;
    out_enew[i] = ma * g_cs_inv[k];
}

// ---------------------------------------------------------------------------
// launch
// ---------------------------------------------------------------------------
extern "C" void kernel_launch(void* const* d_in, const int* in_sizes, int n_in,
                              void* d_out, int out_size) {
    const float* X    = (const float*)d_in[0];
    const float* E    = (const float*)d_in[1];
    const float* cssz = (const float*)d_in[2];
    const float* mavg = (const float*)d_in[3];

    float* out = (float*)d_out;
    float* out_z    = out;
    float* out_loss = out + (size_t)N_PTS * DIM;
    float* out_arg  = out_loss + 1;
    float* out_mind = out_arg + N_PTS;
    float* out_enew = out_mind + N_PTS;
    float* out_cs   = out_enew + K_CODES * DIM;
    float* out_ma   = out_cs + K_CODES;

    static bool attr_done = false;
    if (!attr_done) {
        cudaFuncSetAttribute(dist_kernel,
                             cudaFuncAttributeMaxDynamicSharedMemorySize, SM_TOTAL);
        attr_done = true;
    }

    prep_E<<<(K_CODES * DIM) / 256, 256>>>(E);
    prep_X<<<(N_PTS * DIM) / 256, 256>>>(X);
    zero_stats<<<(K_CODES * DIM) / 256, 256>>>();
    dist_kernel<<<N_PTS / 128, 256, SM_TOTAL>>>(X, out_arg, out_mind);
    gather_kernel<<<(N_PTS * 16) / 256, 256>>>(E, (float4*)out_z);
    cs_kernel<<<1, 1024>>>(cssz, out_loss, out_cs);
    ema_kernel<<<(K_CODES * DIM) / 256, 256>>>(mavg, out_enew, out_ma);
}

// round 7
// speedup vs baseline: 2.5825x; 1.0622x over previous
#include <cuda_runtime.h>
#include <cuda_bf16.h>
#include <cstdint>

#define K_CODES 1024
#define DIM 64
#define N_PTS 131072
#define GAMMA_F 0.99f
#define ONE_M_GAMMA 0.01f
#define ALPHA_F 1e-9f
#define BETA_F 0.25f

#define CCHUNK 128              // codes per smem chunk
#define ROW_PITCH 144           // bytes per code row in smem (64*2 + 16 pad)
#define SPLIT_STRIDE (CCHUNK * ROW_PITCH)   // 18432
#define SM_B 0
#define SM_ESQ (3 * SPLIT_STRIDE)           // 55296
#define SM_RED (SM_ESQ + CCHUNK * 4)        // 55808
#define SM_TOTAL (SM_RED + 256 * 4)         // 56832

// ---- scratch (__device__ globals; no allocs) ----
__device__ __align__(16) __nv_bfloat16 g_Xs0[N_PTS * DIM];
__device__ __align__(16) __nv_bfloat16 g_Xs1[N_PTS * DIM];
__device__ __align__(16) __nv_bfloat16 g_Xs2[N_PTS * DIM];
__device__ __align__(16) __nv_bfloat16 g_Es0[K_CODES * DIM];
__device__ __align__(16) __nv_bfloat16 g_Es1[K_CODES * DIM];
__device__ __align__(16) __nv_bfloat16 g_Es2[K_CODES * DIM];
__device__ __align__(16) float g_esq[K_CODES];
__device__ float g_xsq[N_PTS];
__device__ float g_counts[K_CODES];
__device__ float g_sums[K_CODES * DIM];
__device__ int   g_amin[N_PTS];
__device__ float g_loss;
__device__ float g_cs_inv[K_CODES];

// mma.sync m16n8k16 bf16 (sm_80+ baseline; valid at compute_103)
#define MMA16816(d, a, b0v, b1v, c)                                          \
    asm volatile("mma.sync.aligned.m16n8k16.row.col.f32.bf16.bf16.f32 "      \
        "{%0,%1,%2,%3}, {%4,%5,%6,%7}, {%8,%9}, {%10,%11,%12,%13};"          \
        : "=f"((d)[0]), "=f"((d)[1]), "=f"((d)[2]), "=f"((d)[3])             \
        : "r"((a)[0]), "r"((a)[1]), "r"((a)[2]), "r"((a)[3]),                \
          "r"(b0v), "r"(b1v),                                                \
          "f"((c)[0]), "f"((c)[1]), "f"((c)[2]), "f"((c)[3]))

#define LDSM_X4(r, addr)                                                     \
    asm volatile("ldmatrix.sync.aligned.m8n8.x4.shared.b16 {%0,%1,%2,%3}, [%4];" \
        : "=r"((r)[0]), "=r"((r)[1]), "=r"((r)[2]), "=r"((r)[3])             \
        : "r"(addr))

__device__ __forceinline__ uint32_t smem_u32(const void* p) {
    uint32_t a;
    asm("{ .reg .u64 t; cvta.to.shared.u64 t, %1; cvt.u32.u64 %0, t; }"
        : "=r"(a) : "l"(p));
    return a;
}

// ---------------------------------------------------------------------------
// prep_E: 3-term bf16 splits of e + esq.  grid = K*DIM/256, block 256.
// ---------------------------------------------------------------------------
__global__ void prep_E(const float* __restrict__ E) {
    __shared__ float ws[8];
    int e = blockIdx.x * 256 + threadIdx.x;
    float v = E[e];

    __nv_bfloat16 h0 = __float2bfloat16(v);
    float r1 = v - __bfloat162float(h0);
    __nv_bfloat16 h1 = __float2bfloat16(r1);
    float r2 = r1 - __bfloat162float(h1);
    __nv_bfloat16 h2 = __float2bfloat16(r2);
    g_Es0[e] = h0; g_Es1[e] = h1; g_Es2[e] = h2;

    float sq = v * v;
    #pragma unroll
    for (int o = 16; o > 0; o >>= 1) sq += __shfl_xor_sync(0xffffffffu, sq, o);
    if ((threadIdx.x & 31) == 0) ws[threadIdx.x >> 5] = sq;
    __syncthreads();
    if ((threadIdx.x & 63) == 0) {
        int g = threadIdx.x >> 6;
        g_esq[e >> 6] = ws[2 * g] + ws[2 * g + 1];
    }
}

// ---------------------------------------------------------------------------
// prep_X: 3-term bf16 splits of (-2x) + xsq.  grid = N*DIM/256.
// ---------------------------------------------------------------------------
__global__ void prep_X(const float* __restrict__ X) {
    __shared__ float ws[8];
    int e = blockIdx.x * 256 + threadIdx.x;
    float x = X[e];
    float y = -2.0f * x;

    __nv_bfloat16 h0 = __float2bfloat16(y);
    float r1 = y - __bfloat162float(h0);
    __nv_bfloat16 h1 = __float2bfloat16(r1);
    float r2 = r1 - __bfloat162float(h1);
    __nv_bfloat16 h2 = __float2bfloat16(r2);
    g_Xs0[e] = h0; g_Xs1[e] = h1; g_Xs2[e] = h2;

    float sq = x * x;
    #pragma unroll
    for (int o = 16; o > 0; o >>= 1) sq += __shfl_xor_sync(0xffffffffu, sq, o);
    if ((threadIdx.x & 31) == 0) ws[threadIdx.x >> 5] = sq;
    __syncthreads();
    if ((threadIdx.x & 63) == 0) {
        int g = threadIdx.x >> 6;
        g_xsq[e >> 6] = ws[2 * g] + ws[2 * g + 1];
    }
}

__global__ void zero_stats() {
    int i = blockIdx.x * 256 + threadIdx.x;
    g_sums[i] = 0.0f;
    if (i < K_CODES) g_counts[i] = 0.0f;
    if (i == 0) g_loss = 0.0f;
}

// ---------------------------------------------------------------------------
// dist kernel: HMMA bf16 3-split, key = esq - 2*x.e, argmin + stats.
// 256 threads = 8 warps x 16 points = 128 points/CTA. grid = N/128.
// B fragments via ldmatrix.x4 (6 per 8-code block instead of 24 scalar LDS).
// ---------------------------------------------------------------------------
__global__ void __launch_bounds__(256, 2)
dist_kernel(const float* __restrict__ X,
            float* __restrict__ out_arg, float* __restrict__ out_mind) {
    extern __shared__ char smem[];
    const uint32_t sbase = smem_u32(smem);
    const int tid = threadIdx.x;
    const int wid = tid >> 5;
    const int lane = tid & 31;
    const int g = lane >> 2;          // 0..7
    const int q = lane & 3;           // 0..3
    const int tileRow = blockIdx.x * 128 + wid * 16;
    const int row0 = tileRow + g;
    const int row1 = row0 + 8;

    // per-lane ldmatrix row offset: tile t = lane>>3 (t0..t3 = kcpair {lo,hi}),
    // row r = lane&7 (code within 8-block)
    const int lt = lane >> 3;         // tile index in x4
    const int lr = lane & 7;          // row within tile
    const uint32_t rowoff = (uint32_t)(lr * ROW_PITCH + (lt >> 1) * 32 + (lt & 1) * 16);

    // ---- A fragments: 3 splits x 4 kchunks x 4 regs, resident all loop ----
    unsigned A[3][4][4];
    {
        const __nv_bfloat16* xs[3] = {g_Xs0, g_Xs1, g_Xs2};
        #pragma unroll
        for (int s = 0; s < 3; s++) {
            #pragma unroll
            for (int kc = 0; kc < 4; kc++) {
                size_t b0 = (size_t)row0 * DIM + kc * 16 + q * 2;
                size_t b1 = (size_t)row1 * DIM + kc * 16 + q * 2;
                A[s][kc][0] = *(const unsigned*)(xs[s] + b0);
                A[s][kc][1] = *(const unsigned*)(xs[s] + b1);
                A[s][kc][2] = *(const unsigned*)(xs[s] + b0 + 8);
                A[s][kc][3] = *(const unsigned*)(xs[s] + b1 + 8);
            }
        }
    }

    float zero4[4] = {0.0f, 0.0f, 0.0f, 0.0f};
    float best0 = 3.4e38f, best1 = 3.4e38f;
    int idx0 = 0, idx1 = 0;

    for (int chunk = 0; chunk < K_CODES / CCHUNK; chunk++) {
        __syncthreads();
        // stage B chunk (3 splits, 128 codes, 144B pitch) + esq
        {
            const __nv_bfloat16* es[3] = {g_Es0, g_Es1, g_Es2};
            for (int i = tid; i < 3 * CCHUNK * 8; i += 256) {
                int s = i >> 10;
                int r = i & 1023;
                int n = r >> 3, c = r & 7;
                const uint4* src = (const uint4*)(es[s] + (size_t)chunk * CCHUNK * DIM);
                *(uint4*)(smem + SM_B + s * SPLIT_STRIDE + n * ROW_PITCH + c * 16) = src[r];
            }
            if (tid < CCHUNK / 4)
                ((uint4*)(smem + SM_ESQ))[tid] =
                    ((const uint4*)(g_esq + chunk * CCHUNK))[tid];
        }
        __syncthreads();

        #pragma unroll 4
        for (int nb = 0; nb < CCHUNK / 8; nb++) {
            // B fragments: per split, 2x ldmatrix.x4 covering 4 kchunks
            // Bs[s][2*kc] = b0(kc), Bs[s][2*kc+1] = b1(kc)
            unsigned B0[8], B1[8], B2[8];
            {
                uint32_t a = sbase + SM_B + (uint32_t)(nb * 8 * ROW_PITCH) + rowoff;
                LDSM_X4(B0, a);          // split0 kc0,kc1
                LDSM_X4(B0 + 4, a + 64); // split0 kc2,kc3
                a += SPLIT_STRIDE;
                LDSM_X4(B1, a);
                LDSM_X4(B1 + 4, a + 64);
                a += SPLIT_STRIDE;
                LDSM_X4(B2, a);
                LDSM_X4(B2 + 4, a + 64);
            }

            float cacc[4][4];
            #pragma unroll
            for (int kc = 0; kc < 4; kc++) {
                unsigned b00 = B0[2 * kc], b01 = B0[2 * kc + 1];
                unsigned b10 = B1[2 * kc], b11 = B1[2 * kc + 1];
                unsigned b20 = B2[2 * kc], b21 = B2[2 * kc + 1];
                MMA16816(cacc[kc], A[0][kc], b00, b01, zero4);    // x0*e0
                MMA16816(cacc[kc], A[0][kc], b10, b11, cacc[kc]); // x0*e1
                MMA16816(cacc[kc], A[1][kc], b00, b01, cacc[kc]); // x1*e0
                MMA16816(cacc[kc], A[0][kc], b20, b21, cacc[kc]); // x0*e2
                MMA16816(cacc[kc], A[1][kc], b10, b11, cacc[kc]); // x1*e1
                MMA16816(cacc[kc], A[2][kc], b00, b01, cacc[kc]); // x2*e0
            }

            float2 eq = *(const float2*)(smem + SM_ESQ + (nb * 8 + 2 * q) * 4);
            float k0 = ((cacc[0][0] + cacc[1][0]) + (cacc[2][0] + cacc[3][0])) + eq.x;
            float k1 = ((cacc[0][1] + cacc[1][1]) + (cacc[2][1] + cacc[3][1])) + eq.y;
            float k2 = ((cacc[0][2] + cacc[1][2]) + (cacc[2][2] + cacc[3][2])) + eq.x;
            float k3 = ((cacc[0][3] + cacc[1][3]) + (cacc[2][3] + cacc[3][3])) + eq.y;

            int col = chunk * CCHUNK + nb * 8 + 2 * q;
            if (k0 < best0) { best0 = k0; idx0 = col; }        // ascending: first-min
            if (k1 < best0) { best0 = k1; idx0 = col + 1; }
            if (k2 < best1) { best1 = k2; idx1 = col; }
            if (k3 < best1) { best1 = k3; idx1 = col + 1; }
        }
    }

    // ---- combine across the 4 quad lanes (cols), tie -> lower index ----
    #pragma unroll
    for (int o = 1; o < 4; o <<= 1) {
        float ob = __shfl_xor_sync(0xffffffffu, best0, o);
        int   oi = __shfl_xor_sync(0xffffffffu, idx0,  o);
        if (ob < best0 || (ob == best0 && oi < idx0)) { best0 = ob; idx0 = oi; }
        ob = __shfl_xor_sync(0xffffffffu, best1, o);
        oi = __shfl_xor_sync(0xffffffffu, idx1,  o);
        if (ob < best1 || (ob == best1 && oi < idx1)) { best1 = ob; idx1 = oi; }
    }

    float lsum = 0.0f;
    if (q == 0) {
        float m0 = g_xsq[row0] + best0;
        float m1 = g_xsq[row1] + best1;
        out_arg[row0]  = (float)idx0;  out_arg[row1]  = (float)idx1;
        out_mind[row0] = m0;           out_mind[row1] = m1;
        g_amin[row0]   = idx0;         g_amin[row1]   = idx1;
        atomicAdd(&g_counts[idx0], 1.0f);
        atomicAdd(&g_counts[idx1], 1.0f);
        lsum = m0 + m1;

        const float4* xr0 = (const float4*)(X + (size_t)row0 * DIM);
        const float4* xr1 = (const float4*)(X + (size_t)row1 * DIM);
        float* sp0 = &g_sums[(size_t)idx0 * DIM];
        float* sp1 = &g_sums[(size_t)idx1 * DIM];
        #pragma unroll
        for (int j = 0; j < 16; j++) {
            float4 v = xr0[j];
            asm volatile("red.global.add.v4.f32 [%0], {%1,%2,%3,%4};"
                         :: "l"(sp0 + 4 * j), "f"(v.x), "f"(v.y), "f"(v.z), "f"(v.w)
                         : "memory");
            v = xr1[j];
            asm volatile("red.global.add.v4.f32 [%0], {%1,%2,%3,%4};"
                         :: "l"(sp1 + 4 * j), "f"(v.x), "f"(v.y), "f"(v.z), "f"(v.w)
                         : "memory");
        }
    }

    float* sred = (float*)(smem + SM_RED);
    __syncthreads();
    sred[tid] = lsum;
    __syncthreads();
    for (int s = 128; s > 0; s >>= 1) {
        if (tid < s) sred[tid] += sred[tid + s];
        __syncthreads();
    }
    if (tid == 0) atomicAdd(&g_loss, sred[0]);
}

// ---------------------------------------------------------------------------
// gather: Z_embs = E[argmin]
// ---------------------------------------------------------------------------
__global__ void gather_kernel(const float* __restrict__ E, float4* __restrict__ z) {
    int idx = blockIdx.x * 256 + threadIdx.x;
    int row = idx >> 4;
    int d   = idx & 15;
    z[idx] = ((const float4*)E)[(size_t)g_amin[row] * 16 + d];
}

// ---------------------------------------------------------------------------
// cs + loss
// ---------------------------------------------------------------------------
__global__ void cs_kernel(const float* __restrict__ cluster_sizes,
                          float* __restrict__ out_loss, float* __restrict__ out_cs) {
    __shared__ float warp_sums[32];
    int k = threadIdx.x;
    float cs_pre = GAMMA_F * cluster_sizes[k] + ONE_M_GAMMA * g_counts[k];
    float v = cs_pre;
    #pragma unroll
    for (int o = 16; o > 0; o >>= 1) v += __shfl_xor_sync(0xffffffffu, v, o);
    if ((k & 31) == 0) warp_sums[k >> 5] = v;
    __syncthreads();
    if (k < 32) {
        float w = warp_sums[k];
        #pragma unroll
        for (int o = 16; o > 0; o >>= 1) w += __shfl_xor_sync(0xffffffffu, w, o);
        if (k == 0) warp_sums[0] = w;
    }
    __syncthreads();
    float total = warp_sums[0];
    float denom = 1.0f + ALPHA_F * (float)K_CODES / total;
    float cs = (cs_pre + ALPHA_F) / denom;
    out_cs[k]   = cs;
    g_cs_inv[k] = 1.0f / cs;
    if (k == 0) out_loss[0] = BETA_F * g_loss / (float)N_PTS;
}

// ---------------------------------------------------------------------------
// ma + E_new
// ---------------------------------------------------------------------------
__global__ void ema_kernel(const float* __restrict__ moving_avg,
                           float* __restrict__ out_enew, float* __restrict__ out_ma) {
    int i = blockIdx.x * 256 + threadIdx.x;
    int k = i >> 6;
    float ma = GAMMA_F * moving_avg[i] + ONE_M_GAMMA * g_sums[i];
    out_ma[i]   = ma;
    out_enew[i] = ma * g_cs_inv[k];
}

// ---------------------------------------------------------------------------
// launch
// ---------------------------------------------------------------------------
extern "C" void kernel_launch(void* const* d_in, const int* in_sizes, int n_in,
                              void* d_out, int out_size) {
    const float* X    = (const float*)d_in[0];
    const float* E    = (const float*)d_in[1];
    const float* cssz = (const float*)d_in[2];
    const float* mavg = (const float*)d_in[3];

    float* out = (float*)d_out;
    float* out_z    = out;
    float* out_loss = out + (size_t)N_PTS * DIM;
    float* out_arg  = out_loss + 1;
    float* out_mind = out_arg + N_PTS;
    float* out_enew = out_mind + N_PTS;
    float* out_cs   = out_enew + K_CODES * DIM;
    float* out_ma   = out_cs + K_CODES;

    static bool attr_done = false;
    if (!attr_done) {
        cudaFuncSetAttribute(dist_kernel,
                             cudaFuncAttributeMaxDynamicSharedMemorySize, SM_TOTAL);
        attr_done = true;
    }

    prep_E<<<(K_CODES * DIM) / 256, 256>>>(E);
    prep_X<<<(N_PTS * DIM) / 256, 256>>>(X);
    zero_stats<<<(K_CODES * DIM) / 256, 256>>>();
    dist_kernel<<<N_PTS / 128, 256, SM_TOTAL>>>(X, out_arg, out_mind);
    gather_kernel<<<(N_PTS * 16) / 256, 256>>>(E, (float4*)out_z);
    cs_kernel<<<1, 1024>>>(cssz, out_loss, out_cs);
    ema_kernel<<<(K_CODES * DIM) / 256, 256>>>(mavg, out_enew, out_ma);
}

// round 8
// speedup vs baseline: 2.5942x; 1.0045x over previous
#include <cuda_runtime.h>
#include <cuda_bf16.h>
#include <cstdint>

#define K_CODES 1024
#define DIM 64
#define N_PTS 131072
#define GAMMA_F 0.99f
#define ONE_M_GAMMA 0.01f
#define ALPHA_F 1e-9f
#define BETA_F 0.25f

#define CCHUNK 128              // codes per smem chunk
#define ROW_PITCH 144           // bytes per code row in smem (64*2 + 16 pad)
#define SPLIT_STRIDE (CCHUNK * ROW_PITCH)   // 18432
#define SM_B 0
#define SM_ESQ (3 * SPLIT_STRIDE)           // 55296
#define SM_RED (SM_ESQ + CCHUNK * 4)        // 55808
#define SM_TOTAL (SM_RED + 256 * 4)         // 56832

// ---- scratch (__device__ globals; no allocs) ----
__device__ __align__(16) __nv_bfloat16 g_Xs0[N_PTS * DIM];
__device__ __align__(16) __nv_bfloat16 g_Xs1[N_PTS * DIM];
__device__ __align__(16) __nv_bfloat16 g_Xs2[N_PTS * DIM];
__device__ __align__(16) __nv_bfloat16 g_Es0[K_CODES * DIM];
__device__ __align__(16) __nv_bfloat16 g_Es1[K_CODES * DIM];
__device__ __align__(16) __nv_bfloat16 g_Es2[K_CODES * DIM];
__device__ __align__(16) float g_esq[K_CODES];
__device__ float g_xsq[N_PTS];
__device__ float g_counts[K_CODES];
__device__ float g_sums[K_CODES * DIM];
__device__ float g_loss;
__device__ float g_cs_inv[K_CODES];

// mma.sync m16n8k16 bf16 (sm_80+ baseline; valid at compute_103)
#define MMA16816(d, a, b0v, b1v, c)                                          \
    asm volatile("mma.sync.aligned.m16n8k16.row.col.f32.bf16.bf16.f32 "      \
        "{%0,%1,%2,%3}, {%4,%5,%6,%7}, {%8,%9}, {%10,%11,%12,%13};"          \
        : "=f"((d)[0]), "=f"((d)[1]), "=f"((d)[2]), "=f"((d)[3])             \
        : "r"((a)[0]), "r"((a)[1]), "r"((a)[2]), "r"((a)[3]),                \
          "r"(b0v), "r"(b1v),                                                \
          "f"((c)[0]), "f"((c)[1]), "f"((c)[2]), "f"((c)[3]))

#define LDSM_X4(r, addr)                                                     \
    asm volatile("ldmatrix.sync.aligned.m8n8.x4.shared.b16 {%0,%1,%2,%3}, [%4];" \
        : "=r"((r)[0]), "=r"((r)[1]), "=r"((r)[2]), "=r"((r)[3])             \
        : "r"(addr))

#define CP_ASYNC16(dst, src)                                                 \
    asm volatile("cp.async.cg.shared.global [%0], [%1], 16;"                 \
        :: "r"(dst), "l"(src))
#define CP_COMMIT() asm volatile("cp.async.commit_group;" ::: "memory")
#define CP_WAIT0()  asm volatile("cp.async.wait_group 0;" ::: "memory")

__device__ __forceinline__ uint32_t smem_u32(const void* p) {
    uint32_t a;
    asm("{ .reg .u64 t; cvta.to.shared.u64 t, %1; cvt.u32.u64 %0, t; }"
        : "=r"(a) : "l"(p));
    return a;
}

// ---------------------------------------------------------------------------
// prep_E: 3-term bf16 splits of e + esq, + zero stats.  grid = K*DIM/256.
// ---------------------------------------------------------------------------
__global__ void prep_E(const float* __restrict__ E) {
    __shared__ float ws[8];
    int e = blockIdx.x * 256 + threadIdx.x;
    float v = E[e];

    __nv_bfloat16 h0 = __float2bfloat16(v);
    float r1 = v - __bfloat162float(h0);
    __nv_bfloat16 h1 = __float2bfloat16(r1);
    float r2 = r1 - __bfloat162float(h1);
    __nv_bfloat16 h2 = __float2bfloat16(r2);
    g_Es0[e] = h0; g_Es1[e] = h1; g_Es2[e] = h2;

    g_sums[e] = 0.0f;
    if (e < K_CODES) g_counts[e] = 0.0f;
    if (e == 0) g_loss = 0.0f;

    float sq = v * v;
    #pragma unroll
    for (int o = 16; o > 0; o >>= 1) sq += __shfl_xor_sync(0xffffffffu, sq, o);
    if ((threadIdx.x & 31) == 0) ws[threadIdx.x >> 5] = sq;
    __syncthreads();
    if ((threadIdx.x & 63) == 0) {
        int g = threadIdx.x >> 6;
        g_esq[e >> 6] = ws[2 * g] + ws[2 * g + 1];
    }
}

// ---------------------------------------------------------------------------
// prep_X: 3-term bf16 splits of (-2x) + xsq.  grid = N*DIM/256.
// ---------------------------------------------------------------------------
__global__ void prep_X(const float* __restrict__ X) {
    __shared__ float ws[8];
    int e = blockIdx.x * 256 + threadIdx.x;
    float x = X[e];
    float y = -2.0f * x;

    __nv_bfloat16 h0 = __float2bfloat16(y);
    float r1 = y - __bfloat162float(h0);
    __nv_bfloat16 h1 = __float2bfloat16(r1);
    float r2 = r1 - __bfloat162float(h1);
    __nv_bfloat16 h2 = __float2bfloat16(r2);
    g_Xs0[e] = h0; g_Xs1[e] = h1; g_Xs2[e] = h2;

    float sq = x * x;
    #pragma unroll
    for (int o = 16; o > 0; o >>= 1) sq += __shfl_xor_sync(0xffffffffu, sq, o);
    if ((threadIdx.x & 31) == 0) ws[threadIdx.x >> 5] = sq;
    __syncthreads();
    if ((threadIdx.x & 63) == 0) {
        int g = threadIdx.x >> 6;
        g_xsq[e >> 6] = ws[2 * g] + ws[2 * g + 1];
    }
}

// ---------------------------------------------------------------------------
// dist kernel: HMMA bf16 3-split, key = esq - 2*x.e, argmin + stats + gather.
// 256 threads = 8 warps x 16 points = 128 points/CTA. grid = N/128.
// ---------------------------------------------------------------------------
__global__ void __launch_bounds__(256, 2)
dist_kernel(const float* __restrict__ X, const float* __restrict__ E,
            float4* __restrict__ out_z,
            float* __restrict__ out_arg, float* __restrict__ out_mind) {
    extern __shared__ char smem[];
    const uint32_t sbase = smem_u32(smem);
    const int tid = threadIdx.x;
    const int wid = tid >> 5;
    const int lane = tid & 31;
    const int g = lane >> 2;          // 0..7
    const int q = lane & 3;           // 0..3
    const int tileRow = blockIdx.x * 128 + wid * 16;
    const int row0 = tileRow + g;
    const int row1 = row0 + 8;

    // per-lane ldmatrix row offset (tile t = lane>>3, row r = lane&7)
    const int lt = lane >> 3;
    const int lr = lane & 7;
    const uint32_t rowoff = (uint32_t)(lr * ROW_PITCH + (lt >> 1) * 32 + (lt & 1) * 16);

    // ---- A fragments: 3 splits x 4 kchunks x 4 regs, resident all loop ----
    unsigned A[3][4][4];
    {
        const __nv_bfloat16* xs[3] = {g_Xs0, g_Xs1, g_Xs2};
        #pragma unroll
        for (int s = 0; s < 3; s++) {
            #pragma unroll
            for (int kc = 0; kc < 4; kc++) {
                size_t b0 = (size_t)row0 * DIM + kc * 16 + q * 2;
                size_t b1 = (size_t)row1 * DIM + kc * 16 + q * 2;
                A[s][kc][0] = *(const unsigned*)(xs[s] + b0);
                A[s][kc][1] = *(const unsigned*)(xs[s] + b1);
                A[s][kc][2] = *(const unsigned*)(xs[s] + b0 + 8);
                A[s][kc][3] = *(const unsigned*)(xs[s] + b1 + 8);
            }
        }
    }

    float zero4[4] = {0.0f, 0.0f, 0.0f, 0.0f};
    float best0 = 3.4e38f, best1 = 3.4e38f;
    int idx0 = 0, idx1 = 0;

    for (int chunk = 0; chunk < K_CODES / CCHUNK; chunk++) {
        __syncthreads();
        // stage B chunk (3 splits, 128 codes, 144B pitch) + esq via cp.async
        {
            const __nv_bfloat16* es[3] = {g_Es0, g_Es1, g_Es2};
            #pragma unroll
            for (int ii = 0; ii < 12; ii++) {
                int i = tid + ii * 256;
                int s = i >> 10;
                int r = i & 1023;
                int n = r >> 3, c = r & 7;
                uint32_t dst = sbase + SM_B + s * SPLIT_STRIDE + n * ROW_PITCH + c * 16;
                const void* src = es[s] + (size_t)chunk * CCHUNK * DIM + r * 8;
                CP_ASYNC16(dst, src);
            }
            if (tid < 32)
                CP_ASYNC16(sbase + SM_ESQ + tid * 16, g_esq + chunk * CCHUNK + tid * 4);
            CP_COMMIT();
            CP_WAIT0();
        }
        __syncthreads();

        #pragma unroll 8
        for (int nb = 0; nb < CCHUNK / 8; nb++) {
            unsigned B0[8], B1[8], B2[8];
            {
                uint32_t a = sbase + SM_B + (uint32_t)(nb * 8 * ROW_PITCH) + rowoff;
                LDSM_X4(B0, a);
                LDSM_X4(B0 + 4, a + 64);
                a += SPLIT_STRIDE;
                LDSM_X4(B1, a);
                LDSM_X4(B1 + 4, a + 64);
                a += SPLIT_STRIDE;
                LDSM_X4(B2, a);
                LDSM_X4(B2 + 4, a + 64);
            }

            float cacc[4][4];
            #pragma unroll
            for (int kc = 0; kc < 4; kc++) {
                unsigned b00 = B0[2 * kc], b01 = B0[2 * kc + 1];
                unsigned b10 = B1[2 * kc], b11 = B1[2 * kc + 1];
                unsigned b20 = B2[2 * kc], b21 = B2[2 * kc + 1];
                MMA16816(cacc[kc], A[0][kc], b00, b01, zero4);    // x0*e0
                MMA16816(cacc[kc], A[0][kc], b10, b11, cacc[kc]); // x0*e1
                MMA16816(cacc[kc], A[1][kc], b00, b01, cacc[kc]); // x1*e0
                MMA16816(cacc[kc], A[0][kc], b20, b21, cacc[kc]); // x0*e2
                MMA16816(cacc[kc], A[1][kc], b10, b11, cacc[kc]); // x1*e1
                MMA16816(cacc[kc], A[2][kc], b00, b01, cacc[kc]); // x2*e0
            }

            float2 eq = *(const float2*)(smem + SM_ESQ + (nb * 8 + 2 * q) * 4);
            float k0 = ((cacc[0][0] + cacc[1][0]) + (cacc[2][0] + cacc[3][0])) + eq.x;
            float k1 = ((cacc[0][1] + cacc[1][1]) + (cacc[2][1] + cacc[3][1])) + eq.y;
            float k2 = ((cacc[0][2] + cacc[1][2]) + (cacc[2][2] + cacc[3][2])) + eq.x;
            float k3 = ((cacc[0][3] + cacc[1][3]) + (cacc[2][3] + cacc[3][3])) + eq.y;

            int col = chunk * CCHUNK + nb * 8 + 2 * q;
            if (k0 < best0) { best0 = k0; idx0 = col; }        // ascending: first-min
            if (k1 < best0) { best0 = k1; idx0 = col + 1; }
            if (k2 < best1) { best1 = k2; idx1 = col; }
            if (k3 < best1) { best1 = k3; idx1 = col + 1; }
        }
    }

    // ---- combine across the 4 quad lanes (cols), tie -> lower index ----
    #pragma unroll
    for (int o = 1; o < 4; o <<= 1) {
        float ob = __shfl_xor_sync(0xffffffffu, best0, o);
        int   oi = __shfl_xor_sync(0xffffffffu, idx0,  o);
        if (ob < best0 || (ob == best0 && oi < idx0)) { best0 = ob; idx0 = oi; }
        ob = __shfl_xor_sync(0xffffffffu, best1, o);
        oi = __shfl_xor_sync(0xffffffffu, idx1,  o);
        if (ob < best1 || (ob == best1 && oi < idx1)) { best1 = ob; idx1 = oi; }
    }

    // ---- fused gather: all 4 quad lanes copy E[argmin] rows to Z ----
    {
        const float4* e0 = (const float4*)E + (size_t)idx0 * 16;
        const float4* e1 = (const float4*)E + (size_t)idx1 * 16;
        float4* z0 = out_z + (size_t)row0 * 16;
        float4* z1 = out_z + (size_t)row1 * 16;
        #pragma unroll
        for (int j = 0; j < 4; j++) {
            z0[q + 4 * j] = e0[q + 4 * j];
            z1[q + 4 * j] = e1[q + 4 * j];
        }
    }

    float lsum = 0.0f;
    if (q == 0) {
        float m0 = g_xsq[row0] + best0;
        float m1 = g_xsq[row1] + best1;
        out_arg[row0]  = (float)idx0;  out_arg[row1]  = (float)idx1;
        out_mind[row0] = m0;           out_mind[row1] = m1;
        atomicAdd(&g_counts[idx0], 1.0f);
        atomicAdd(&g_counts[idx1], 1.0f);
        lsum = m0 + m1;

        const float4* xr0 = (const float4*)(X + (size_t)row0 * DIM);
        const float4* xr1 = (const float4*)(X + (size_t)row1 * DIM);
        float* sp0 = &g_sums[(size_t)idx0 * DIM];
        float* sp1 = &g_sums[(size_t)idx1 * DIM];
        #pragma unroll
        for (int j = 0; j < 16; j++) {
            float4 v = xr0[j];
            asm volatile("red.global.add.v4.f32 [%0], {%1,%2,%3,%4};"
                         :: "l"(sp0 + 4 * j), "f"(v.x), "f"(v.y), "f"(v.z), "f"(v.w)
                         : "memory");
            v = xr1[j];
            asm volatile("red.global.add.v4.f32 [%0], {%1,%2,%3,%4};"
                         :: "l"(sp1 + 4 * j), "f"(v.x), "f"(v.y), "f"(v.z), "f"(v.w)
                         : "memory");
        }
    }

    float* sred = (float*)(smem + SM_RED);
    __syncthreads();
    sred[tid] = lsum;
    __syncthreads();
    for (int s = 128; s > 0; s >>= 1) {
        if (tid < s) sred[tid] += sred[tid + s];
        __syncthreads();
    }
    if (tid == 0) atomicAdd(&g_loss, sred[0]);
}

// ---------------------------------------------------------------------------
// cs + loss
// ---------------------------------------------------------------------------
__global__ void cs_kernel(const float* __restrict__ cluster_sizes,
                          float* __restrict__ out_loss, float* __restrict__ out_cs) {
    __shared__ float warp_sums[32];
    int k = threadIdx.x;
    float cs_pre = GAMMA_F * cluster_sizes[k] + ONE_M_GAMMA * g_counts[k];
    float v = cs_pre;
    #pragma unroll
    for (int o = 16; o > 0; o >>= 1) v += __shfl_xor_sync(0xffffffffu, v, o);
    if ((k & 31) == 0) warp_sums[k >> 5] = v;
    __syncthreads();
    if (k < 32) {
        float w = warp_sums[k];
        #pragma unroll
        for (int o = 16; o > 0; o >>= 1) w += __shfl_xor_sync(0xffffffffu, w, o);
        if (k == 0) warp_sums[0] = w;
    }
    __syncthreads();
    float total = warp_sums[0];
    float denom = 1.0f + ALPHA_F * (float)K_CODES / total;
    float cs = (cs_pre + ALPHA_F) / denom;
    out_cs[k]   = cs;
    g_cs_inv[k] = 1.0f / cs;
    if (k == 0) out_loss[0] = BETA_F * g_loss / (float)N_PTS;
}

// ---------------------------------------------------------------------------
// ma + E_new
// ---------------------------------------------------------------------------
__global__ void ema_kernel(const float* __restrict__ moving_avg,
                           float* __restrict__ out_enew, float* __restrict__ out_ma) {
    int i = blockIdx.x * 256 + threadIdx.x;
    int k = i >> 6;
    float ma = GAMMA_F * moving_avg[i] + ONE_M_GAMMA * g_sums[i];
    out_ma[i]   = ma;
    out_enew[i] = ma * g_cs_inv[k];
}

// ---------------------------------------------------------------------------
// launch
// ---------------------------------------------------------------------------
extern "C" void kernel_launch(void* const* d_in, const int* in_sizes, int n_in,
                              void* d_out, int out_size) {
    const float* X    = (const float*)d_in[0];
    const float* E    = (const float*)d_in[1];
    const float* cssz = (const float*)d_in[2];
    const float* mavg = (const float*)d_in[3];

    float* out = (float*)d_out;
    float* out_z    = out;
    float* out_loss = out + (size_t)N_PTS * DIM;
    float* out_arg  = out_loss + 1;
    float* out_mind = out_arg + N_PTS;
    float* out_enew = out_mind + N_PTS;
    float* out_cs   = out_enew + K_CODES * DIM;
    float* out_ma   = out_cs + K_CODES;

    static bool attr_done = false;
    if (!attr_done) {
        cudaFuncSetAttribute(dist_kernel,
                             cudaFuncAttributeMaxDynamicSharedMemorySize, SM_TOTAL);
        attr_done = true;
    }

    prep_E<<<(K_CODES * DIM) / 256, 256>>>(E);
    prep_X<<<(N_PTS * DIM) / 256, 256>>>(X);
    dist_kernel<<<N_PTS / 128, 256, SM_TOTAL>>>(X, E, (float4*)out_z,
                                                out_arg, out_mind);
    cs_kernel<<<1, 1024>>>(cssz, out_loss, out_cs);
    ema_kernel<<<(K_CODES * DIM) / 256, 256>>>(mavg, out_enew, out_ma);
}

// round 9
// speedup vs baseline: 3.0423x; 1.1727x over previous
#include <cuda_runtime.h>
#include <cuda_bf16.h>
#include <cstdint>

#define K_CODES 1024
#define DIM 64
#define N_PTS 131072
#define GAMMA_F 0.99f
#define ONE_M_GAMMA 0.01f
#define ALPHA_F 1e-9f
#define BETA_F 0.25f

#define CCHUNK 64               // codes per smem chunk (double-buffered)
#define ROW_PITCH 144           // bytes per code row in smem (64*2 + 16 pad)
#define SPLIT_STRIDE (CCHUNK * ROW_PITCH)        // 9216
#define ESQ_OFF (3 * SPLIT_STRIDE)               // 27648
#define BUF_SZ (ESQ_OFF + CCHUNK * 4)            // 27904
#define SM_RED (2 * BUF_SZ)                      // 55808
#define SM_TOTAL (SM_RED + 256 * 4)              // 56832
#define NCHUNKS (K_CODES / CCHUNK)               // 16

// ---- scratch (__device__ globals; no allocs) ----
__device__ __align__(16) __nv_bfloat16 g_Es0[K_CODES * DIM];
__device__ __align__(16) __nv_bfloat16 g_Es1[K_CODES * DIM];
__device__ __align__(16) __nv_bfloat16 g_Es2[K_CODES * DIM];
__device__ __align__(16) float g_esq[K_CODES];
__device__ float g_counts[K_CODES];
__device__ float g_sums[K_CODES * DIM];
__device__ float g_loss;
__device__ float g_cs_inv[K_CODES];

// mma.sync m16n8k16 bf16 (sm_80+ baseline; valid at compute_103)
#define MMA16816(d, a, b0v, b1v, c)                                          \
    asm volatile("mma.sync.aligned.m16n8k16.row.col.f32.bf16.bf16.f32 "      \
        "{%0,%1,%2,%3}, {%4,%5,%6,%7}, {%8,%9}, {%10,%11,%12,%13};"          \
        : "=f"((d)[0]), "=f"((d)[1]), "=f"((d)[2]), "=f"((d)[3])             \
        : "r"((a)[0]), "r"((a)[1]), "r"((a)[2]), "r"((a)[3]),                \
          "r"(b0v), "r"(b1v),                                                \
          "f"((c)[0]), "f"((c)[1]), "f"((c)[2]), "f"((c)[3]))

#define LDSM_X4(r, addr)                                                     \
    asm volatile("ldmatrix.sync.aligned.m8n8.x4.shared.b16 {%0,%1,%2,%3}, [%4];" \
        : "=r"((r)[0]), "=r"((r)[1]), "=r"((r)[2]), "=r"((r)[3])             \
        : "r"(addr))

#define CP_ASYNC16(dst, src)                                                 \
    asm volatile("cp.async.cg.shared.global [%0], [%1], 16;"                 \
        :: "r"(dst), "l"(src))
#define CP_COMMIT()  asm volatile("cp.async.commit_group;" ::: "memory")
#define CP_WAIT(n)   asm volatile("cp.async.wait_group %0;" :: "n"(n) : "memory")

__device__ __forceinline__ uint32_t smem_u32(const void* p) {
    uint32_t a;
    asm("{ .reg .u64 t; cvta.to.shared.u64 t, %1; cvt.u32.u64 %0, t; }"
        : "=r"(a) : "l"(p));
    return a;
}
__device__ __forceinline__ unsigned pack_bf2(__nv_bfloat16 lo, __nv_bfloat16 hi) {
    __nv_bfloat162 v = __halves2bfloat162(lo, hi);
    return *(unsigned*)&v;
}

// ---------------------------------------------------------------------------
// prep_E: 3-term bf16 splits of e + esq, + zero stats.  grid = K*DIM/256.
// ---------------------------------------------------------------------------
__global__ void prep_E(const float* __restrict__ E) {
    __shared__ float ws[8];
    int e = blockIdx.x * 256 + threadIdx.x;
    float v = E[e];

    __nv_bfloat16 h0 = __float2bfloat16(v);
    float r1 = v - __bfloat162float(h0);
    __nv_bfloat16 h1 = __float2bfloat16(r1);
    float r2 = r1 - __bfloat162float(h1);
    __nv_bfloat16 h2 = __float2bfloat16(r2);
    g_Es0[e] = h0; g_Es1[e] = h1; g_Es2[e] = h2;

    g_sums[e] = 0.0f;
    if (e < K_CODES) g_counts[e] = 0.0f;
    if (e == 0) g_loss = 0.0f;

    float sq = v * v;
    #pragma unroll
    for (int o = 16; o > 0; o >>= 1) sq += __shfl_xor_sync(0xffffffffu, sq, o);
    if ((threadIdx.x & 31) == 0) ws[threadIdx.x >> 5] = sq;
    __syncthreads();
    if ((threadIdx.x & 63) == 0) {
        int g = threadIdx.x >> 6;
        g_esq[e >> 6] = ws[2 * g] + ws[2 * g + 1];
    }
}

// ---------------------------------------------------------------------------
// dist kernel: HMMA bf16 3-split, key = esq - 2*x.e, argmin + stats + gather.
// In-register A split (no prep_X); double-buffered cp.async B pipeline.
// 256 threads = 8 warps x 16 points = 128 points/CTA. grid = N/128.
// ---------------------------------------------------------------------------
__global__ void __launch_bounds__(256, 2)
dist_kernel(const float* __restrict__ X, const float* __restrict__ E,
            float4* __restrict__ out_z,
            float* __restrict__ out_arg, float* __restrict__ out_mind) {
    extern __shared__ char smem[];
    const uint32_t sbase = smem_u32(smem);
    const int tid = threadIdx.x;
    const int wid = tid >> 5;
    const int lane = tid & 31;
    const int g = lane >> 2;          // 0..7
    const int q = lane & 3;           // 0..3
    const int tileRow = blockIdx.x * 128 + wid * 16;
    const int row0 = tileRow + g;
    const int row1 = row0 + 8;

    // per-lane ldmatrix row offset (tile t = lane>>3, row r = lane&7)
    const int lt = lane >> 3;
    const int lr = lane & 7;
    const uint32_t rowoff = (uint32_t)(lr * ROW_PITCH + (lt >> 1) * 32 + (lt & 1) * 16);

    // ---- kick off chunk-0 B staging before doing A-split math ----
    const __nv_bfloat16* es[3] = {g_Es0, g_Es1, g_Es2};
    auto stage = [&](int chunk) {
        uint32_t bb = sbase + (uint32_t)((chunk & 1) * BUF_SZ);
        #pragma unroll
        for (int ii = 0; ii < 6; ii++) {
            int i = tid + ii * 256;       // 0..1535 = 3 splits x 512 uint4
            int s = i >> 9;
            int r = i & 511;
            int n = r >> 3, c = r & 7;
            CP_ASYNC16(bb + s * SPLIT_STRIDE + n * ROW_PITCH + c * 16,
                       es[s] + (size_t)chunk * CCHUNK * DIM + r * 8);
        }
        if (tid < CCHUNK / 4)
            CP_ASYNC16(bb + ESQ_OFF + tid * 16, g_esq + chunk * CCHUNK + tid * 4);
        CP_COMMIT();
    };
    stage(0);

    // ---- A fragments built in-register from X (3-way split of -2x) ----
    unsigned A[3][4][4];
    float xsq0 = 0.0f, xsq1 = 0.0f;
    #pragma unroll
    for (int kc = 0; kc < 4; kc++) {
        float2 v00 = *(const float2*)(X + (size_t)row0 * DIM + kc * 16 + q * 2);
        float2 v01 = *(const float2*)(X + (size_t)row0 * DIM + kc * 16 + q * 2 + 8);
        float2 v10 = *(const float2*)(X + (size_t)row1 * DIM + kc * 16 + q * 2);
        float2 v11 = *(const float2*)(X + (size_t)row1 * DIM + kc * 16 + q * 2 + 8);
        xsq0 += v00.x * v00.x + v00.y * v00.y + v01.x * v01.x + v01.y * v01.y;
        xsq1 += v10.x * v10.x + v10.y * v10.y + v11.x * v11.x + v11.y * v11.y;

        const float2 vs[4] = {v00, v10, v01, v11};
        #pragma unroll
        for (int j = 0; j < 4; j++) {
            float ax = -2.0f * vs[j].x, ay = -2.0f * vs[j].y;
            __nv_bfloat16 x0 = __float2bfloat16(ax);
            float rx = ax - __bfloat162float(x0);
            __nv_bfloat16 x1 = __float2bfloat16(rx);
            __nv_bfloat16 x2 = __float2bfloat16(rx - __bfloat162float(x1));
            __nv_bfloat16 y0 = __float2bfloat16(ay);
            float ry = ay - __bfloat162float(y0);
            __nv_bfloat16 y1 = __float2bfloat16(ry);
            __nv_bfloat16 y2 = __float2bfloat16(ry - __bfloat162float(y1));
            A[0][kc][j] = pack_bf2(x0, y0);
            A[1][kc][j] = pack_bf2(x1, y1);
            A[2][kc][j] = pack_bf2(x2, y2);
        }
    }
    // quad-lane reduce for xsq (4 lanes hold disjoint 16-col subsets)
    xsq0 += __shfl_xor_sync(0xffffffffu, xsq0, 1);
    xsq0 += __shfl_xor_sync(0xffffffffu, xsq0, 2);
    xsq1 += __shfl_xor_sync(0xffffffffu, xsq1, 1);
    xsq1 += __shfl_xor_sync(0xffffffffu, xsq1, 2);

    float zero4[4] = {0.0f, 0.0f, 0.0f, 0.0f};
    float best0 = 3.4e38f, best1 = 3.4e38f;
    int idx0 = 0, idx1 = 0;

    for (int chunk = 0; chunk < NCHUNKS; chunk++) {
        if (chunk + 1 < NCHUNKS) { stage(chunk + 1); CP_WAIT(1); }
        else                     { CP_WAIT(0); }
        __syncthreads();

        const uint32_t bb = sbase + (uint32_t)((chunk & 1) * BUF_SZ);
        const char* ebase = smem + (chunk & 1) * BUF_SZ + ESQ_OFF;

        #pragma unroll
        for (int nb = 0; nb < CCHUNK / 8; nb++) {
            unsigned B0[8], B1[8], B2[8];
            {
                uint32_t a = bb + (uint32_t)(nb * 8 * ROW_PITCH) + rowoff;
                LDSM_X4(B0, a);
                LDSM_X4(B0 + 4, a + 64);
                a += SPLIT_STRIDE;
                LDSM_X4(B1, a);
                LDSM_X4(B1 + 4, a + 64);
                a += SPLIT_STRIDE;
                LDSM_X4(B2, a);
                LDSM_X4(B2 + 4, a + 64);
            }

            float cacc[4][4];
            #pragma unroll
            for (int kc = 0; kc < 4; kc++) {
                unsigned b00 = B0[2 * kc], b01 = B0[2 * kc + 1];
                unsigned b10 = B1[2 * kc], b11 = B1[2 * kc + 1];
                unsigned b20 = B2[2 * kc], b21 = B2[2 * kc + 1];
                MMA16816(cacc[kc], A[0][kc], b00, b01, zero4);    // x0*e0
                MMA16816(cacc[kc], A[0][kc], b10, b11, cacc[kc]); // x0*e1
                MMA16816(cacc[kc], A[1][kc], b00, b01, cacc[kc]); // x1*e0
                MMA16816(cacc[kc], A[0][kc], b20, b21, cacc[kc]); // x0*e2
                MMA16816(cacc[kc], A[1][kc], b10, b11, cacc[kc]); // x1*e1
                MMA16816(cacc[kc], A[2][kc], b00, b01, cacc[kc]); // x2*e0
            }

            float2 eq = *(const float2*)(ebase + (nb * 8 + 2 * q) * 4);
            float k0 = ((cacc[0][0] + cacc[1][0]) + (cacc[2][0] + cacc[3][0])) + eq.x;
            float k1 = ((cacc[0][1] + cacc[1][1]) + (cacc[2][1] + cacc[3][1])) + eq.y;
            float k2 = ((cacc[0][2] + cacc[1][2]) + (cacc[2][2] + cacc[3][2])) + eq.x;
            float k3 = ((cacc[0][3] + cacc[1][3]) + (cacc[2][3] + cacc[3][3])) + eq.y;

            int col = chunk * CCHUNK + nb * 8 + 2 * q;
            if (k0 < best0) { best0 = k0; idx0 = col; }        // ascending: first-min
            if (k1 < best0) { best0 = k1; idx0 = col + 1; }
            if (k2 < best1) { best1 = k2; idx1 = col; }
            if (k3 < best1) { best1 = k3; idx1 = col + 1; }
        }
        __syncthreads();   // buffer (chunk&1) free for prefetch at chunk+1
    }

    // ---- combine across the 4 quad lanes (cols), tie -> lower index ----
    #pragma unroll
    for (int o = 1; o < 4; o <<= 1) {
        float ob = __shfl_xor_sync(0xffffffffu, best0, o);
        int   oi = __shfl_xor_sync(0xffffffffu, idx0,  o);
        if (ob < best0 || (ob == best0 && oi < idx0)) { best0 = ob; idx0 = oi; }
        ob = __shfl_xor_sync(0xffffffffu, best1, o);
        oi = __shfl_xor_sync(0xffffffffu, idx1,  o);
        if (ob < best1 || (ob == best1 && oi < idx1)) { best1 = ob; idx1 = oi; }
    }

    // ---- fused gather: all 4 quad lanes copy E[argmin] rows to Z ----
    {
        const float4* e0 = (const float4*)E + (size_t)idx0 * 16;
        const float4* e1 = (const float4*)E + (size_t)idx1 * 16;
        float4* z0 = out_z + (size_t)row0 * 16;
        float4* z1 = out_z + (size_t)row1 * 16;
        #pragma unroll
        for (int j = 0; j < 4; j++) {
            z0[q + 4 * j] = e0[q + 4 * j];
            z1[q + 4 * j] = e1[q + 4 * j];
        }
    }

    float lsum = 0.0f;
    if (q == 0) {
        float m0 = xsq0 + best0;
        float m1 = xsq1 + best1;
        out_arg[row0]  = (float)idx0;  out_arg[row1]  = (float)idx1;
        out_mind[row0] = m0;           out_mind[row1] = m1;
        atomicAdd(&g_counts[idx0], 1.0f);
        atomicAdd(&g_counts[idx1], 1.0f);
        lsum = m0 + m1;

        const float4* xr0 = (const float4*)(X + (size_t)row0 * DIM);
        const float4* xr1 = (const float4*)(X + (size_t)row1 * DIM);
        float* sp0 = &g_sums[(size_t)idx0 * DIM];
        float* sp1 = &g_sums[(size_t)idx1 * DIM];
        #pragma unroll
        for (int j = 0; j < 16; j++) {
            float4 v = xr0[j];
            asm volatile("red.global.add.v4.f32 [%0], {%1,%2,%3,%4};"
                         :: "l"(sp0 + 4 * j), "f"(v.x), "f"(v.y), "f"(v.z), "f"(v.w)
                         : "memory");
            v = xr1[j];
            asm volatile("red.global.add.v4.f32 [%0], {%1,%2,%3,%4};"
                         :: "l"(sp1 + 4 * j), "f"(v.x), "f"(v.y), "f"(v.z), "f"(v.w)
                         : "memory");
        }
    }

    float* sred = (float*)(smem + SM_RED);
    __syncthreads();
    sred[tid] = lsum;
    __syncthreads();
    for (int s = 128; s > 0; s >>= 1) {
        if (tid < s) sred[tid] += sred[tid + s];
        __syncthreads();
    }
    if (tid == 0) atomicAdd(&g_loss, sred[0]);
}

// ---------------------------------------------------------------------------
// cs + loss
// ---------------------------------------------------------------------------
__global__ void cs_kernel(const float* __restrict__ cluster_sizes,
                          float* __restrict__ out_loss, float* __restrict__ out_cs) {
    __shared__ float warp_sums[32];
    int k = threadIdx.x;
    float cs_pre = GAMMA_F * cluster_sizes[k] + ONE_M_GAMMA * g_counts[k];
    float v = cs_pre;
    #pragma unroll
    for (int o = 16; o > 0; o >>= 1) v += __shfl_xor_sync(0xffffffffu, v, o);
    if ((k & 31) == 0) warp_sums[k >> 5] = v;
    __syncthreads();
    if (k < 32) {
        float w = warp_sums[k];
        #pragma unroll
        for (int o = 16; o > 0; o >>= 1) w += __shfl_xor_sync(0xffffffffu, w, o);
        if (k == 0) warp_sums[0] = w;
    }
    __syncthreads();
    float total = warp_sums[0];
    float denom = 1.0f + ALPHA_F * (float)K_CODES / total;
    float cs = (cs_pre + ALPHA_F) / denom;
    out_cs[k]   = cs;
    g_cs_inv[k] = 1.0f / cs;
    if (k == 0) out_loss[0] = BETA_F * g_loss / (float)N_PTS;
}

// ---------------------------------------------------------------------------
// ma + E_new
// ---------------------------------------------------------------------------
__global__ void ema_kernel(const float* __restrict__ moving_avg,
                           float* __restrict__ out_enew, float* __restrict__ out_ma) {
    int i = blockIdx.x * 256 + threadIdx.x;
    int k = i >> 6;
    float ma = GAMMA_F * moving_avg[i] + ONE_M_GAMMA * g_sums[i];
    out_ma[i]   = ma;
    out_enew[i] = ma * g_cs_inv[k];
}

// ---------------------------------------------------------------------------
// launch
// ---------------------------------------------------------------------------
extern "C" void kernel_launch(void* const* d_in, const int* in_sizes, int n_in,
                              void* d_out, int out_size) {
    const float* X    = (const float*)d_in[0];
    const float* E    = (const float*)d_in[1];
    const float* cssz = (const float*)d_in[2];
    const float* mavg = (const float*)d_in[3];

    float* out = (float*)d_out;
    float* out_z    = out;
    float* out_loss = out + (size_t)N_PTS * DIM;
    float* out_arg  = out_loss + 1;
    float* out_mind = out_arg + N_PTS;
    float* out_enew = out_mind + N_PTS;
    float* out_cs   = out_enew + K_CODES * DIM;
    float* out_ma   = out_cs + K_CODES;

    static bool attr_done = false;
    if (!attr_done) {
        cudaFuncSetAttribute(dist_kernel,
                             cudaFuncAttributeMaxDynamicSharedMemorySize, SM_TOTAL);
        attr_done = true;
    }

    prep_E<<<(K_CODES * DIM) / 256, 256>>>(E);
    dist_kernel<<<N_PTS / 128, 256, SM_TOTAL>>>(X, E, (float4*)out_z,
                                                out_arg, out_mind);
    cs_kernel<<<1, 1024>>>(cssz, out_loss, out_cs);
    ema_kernel<<<(K_CODES * DIM) / 256, 256>>>(mavg, out_enew, out_ma);
}

// round 10
// speedup vs baseline: 4.4560x; 1.4647x over previous
#include <cuda_runtime.h>
#include <cuda_bf16.h>
#include <cuda_fp16.h>
#include <cstdint>

#define K_CODES 1024
#define DIM 64
#define N_PTS 131072
#define GAMMA_F 0.99f
#define ONE_M_GAMMA 0.01f
#define ALPHA_F 1e-9f
#define BETA_F 0.25f

#define CCHUNK 64               // codes per smem chunk (double-buffered)
#define ROW_PITCH 144           // bytes per code row in smem (64*2 + 16 pad)
#define SPLIT_STRIDE (CCHUNK * ROW_PITCH)        // 9216
#define ESQ_OFF (2 * SPLIT_STRIDE)               // 18432
#define BUF_SZ (ESQ_OFF + CCHUNK * 4)            // 18688
#define SM_RED (2 * BUF_SZ)                      // 37376
#define SM_TOTAL (SM_RED + 256 * 4)              // 38400
#define NCHUNKS (K_CODES / CCHUNK)               // 16

// ---- scratch (__device__ globals; no allocs) ----
__device__ __align__(16) __half g_Es0[K_CODES * DIM];
__device__ __align__(16) __half g_Es1[K_CODES * DIM];
__device__ __align__(16) float g_esq[K_CODES];
__device__ float g_counts[K_CODES];
__device__ float g_sums[K_CODES * DIM];
__device__ float g_loss;
__device__ float g_cs_inv[K_CODES];

// mma.sync m16n8k16 fp16 -> f32 (sm_80+ baseline; valid at compute_103)
#define MMA16816(d, a, b0v, b1v, c)                                          \
    asm volatile("mma.sync.aligned.m16n8k16.row.col.f32.f16.f16.f32 "        \
        "{%0,%1,%2,%3}, {%4,%5,%6,%7}, {%8,%9}, {%10,%11,%12,%13};"          \
        : "=f"((d)[0]), "=f"((d)[1]), "=f"((d)[2]), "=f"((d)[3])             \
        : "r"((a)[0]), "r"((a)[1]), "r"((a)[2]), "r"((a)[3]),                \
          "r"(b0v), "r"(b1v),                                                \
          "f"((c)[0]), "f"((c)[1]), "f"((c)[2]), "f"((c)[3]))

#define LDSM_X4(r, addr)                                                     \
    asm volatile("ldmatrix.sync.aligned.m8n8.x4.shared.b16 {%0,%1,%2,%3}, [%4];" \
        : "=r"((r)[0]), "=r"((r)[1]), "=r"((r)[2]), "=r"((r)[3])             \
        : "r"(addr))

#define CP_ASYNC16(dst, src)                                                 \
    asm volatile("cp.async.cg.shared.global [%0], [%1], 16;"                 \
        :: "r"(dst), "l"(src))
#define CP_COMMIT()  asm volatile("cp.async.commit_group;" ::: "memory")
#define CP_WAIT(n)   asm volatile("cp.async.wait_group %0;" :: "n"(n) : "memory")

__device__ __forceinline__ uint32_t smem_u32(const void* p) {
    uint32_t a;
    asm("{ .reg .u64 t; cvta.to.shared.u64 t, %1; cvt.u32.u64 %0, t; }"
        : "=r"(a) : "l"(p));
    return a;
}
__device__ __forceinline__ unsigned pack_h2(__half lo, __half hi) {
    __half2 v = __halves2half2(lo, hi);
    return *(unsigned*)&v;
}

// ---------------------------------------------------------------------------
// prep_E: 2-term fp16 splits of e + esq, + zero stats.  grid = K*DIM/256.
// ---------------------------------------------------------------------------
__global__ void prep_E(const float* __restrict__ E) {
    __shared__ float ws[8];
    int e = blockIdx.x * 256 + threadIdx.x;
    float v = E[e];

    __half h0 = __float2half(v);
    float r1 = v - __half2float(h0);
    __half h1 = __float2half(r1);
    g_Es0[e] = h0; g_Es1[e] = h1;

    g_sums[e] = 0.0f;
    if (e < K_CODES) g_counts[e] = 0.0f;
    if (e == 0) g_loss = 0.0f;

    float sq = v * v;
    #pragma unroll
    for (int o = 16; o > 0; o >>= 1) sq += __shfl_xor_sync(0xffffffffu, sq, o);
    if ((threadIdx.x & 31) == 0) ws[threadIdx.x >> 5] = sq;
    __syncthreads();
    if ((threadIdx.x & 63) == 0) {
        int g = threadIdx.x >> 6;
        g_esq[e >> 6] = ws[2 * g] + ws[2 * g + 1];
    }
}

// ---------------------------------------------------------------------------
// dist kernel: HMMA fp16 2-split (3 products), key = esq - 2*x.e,
// argmin + stats + fused gather. In-register A split; double-buffered cp.async.
// 256 threads = 8 warps x 16 points = 128 points/CTA. grid = N/128.
// ---------------------------------------------------------------------------
__global__ void __launch_bounds__(256, 2)
dist_kernel(const float* __restrict__ X, const float* __restrict__ E,
            float4* __restrict__ out_z,
            float* __restrict__ out_arg, float* __restrict__ out_mind) {
    extern __shared__ char smem[];
    const uint32_t sbase = smem_u32(smem);
    const int tid = threadIdx.x;
    const int wid = tid >> 5;
    const int lane = tid & 31;
    const int g = lane >> 2;          // 0..7
    const int q = lane & 3;           // 0..3
    const int tileRow = blockIdx.x * 128 + wid * 16;
    const int row0 = tileRow + g;
    const int row1 = row0 + 8;

    // per-lane ldmatrix row offset (tile t = lane>>3, row r = lane&7)
    const int lt = lane >> 3;
    const int lr = lane & 7;
    const uint32_t rowoff = (uint32_t)(lr * ROW_PITCH + (lt >> 1) * 32 + (lt & 1) * 16);

    // ---- kick off chunk-0 B staging before doing A-split math ----
    const __half* es[2] = {g_Es0, g_Es1};
    auto stage = [&](int chunk) {
        uint32_t bb = sbase + (uint32_t)((chunk & 1) * BUF_SZ);
        #pragma unroll
        for (int ii = 0; ii < 4; ii++) {
            int i = tid + ii * 256;       // 0..1023 = 2 splits x 512 uint4
            int s = i >> 9;
            int r = i & 511;
            int n = r >> 3, c = r & 7;
            CP_ASYNC16(bb + s * SPLIT_STRIDE + n * ROW_PITCH + c * 16,
                       es[s] + (size_t)chunk * CCHUNK * DIM + r * 8);
        }
        if (tid < CCHUNK / 4)
            CP_ASYNC16(bb + ESQ_OFF + tid * 16, g_esq + chunk * CCHUNK + tid * 4);
        CP_COMMIT();
    };
    stage(0);

    // ---- A fragments built in-register from X (2-way fp16 split of -2x) ----
    unsigned A[2][4][4];
    float xsq0 = 0.0f, xsq1 = 0.0f;
    #pragma unroll
    for (int kc = 0; kc < 4; kc++) {
        float2 v00 = *(const float2*)(X + (size_t)row0 * DIM + kc * 16 + q * 2);
        float2 v01 = *(const float2*)(X + (size_t)row0 * DIM + kc * 16 + q * 2 + 8);
        float2 v10 = *(const float2*)(X + (size_t)row1 * DIM + kc * 16 + q * 2);
        float2 v11 = *(const float2*)(X + (size_t)row1 * DIM + kc * 16 + q * 2 + 8);
        xsq0 += v00.x * v00.x + v00.y * v00.y + v01.x * v01.x + v01.y * v01.y;
        xsq1 += v10.x * v10.x + v10.y * v10.y + v11.x * v11.x + v11.y * v11.y;

        const float2 vs[4] = {v00, v10, v01, v11};
        #pragma unroll
        for (int j = 0; j < 4; j++) {
            float ax = -2.0f * vs[j].x, ay = -2.0f * vs[j].y;
            __half x0 = __float2half(ax);
            __half x1 = __float2half(ax - __half2float(x0));
            __half y0 = __float2half(ay);
            __half y1 = __float2half(ay - __half2float(y0));
            A[0][kc][j] = pack_h2(x0, y0);
            A[1][kc][j] = pack_h2(x1, y1);
        }
    }
    // quad-lane reduce for xsq (4 lanes hold disjoint 16-col subsets)
    xsq0 += __shfl_xor_sync(0xffffffffu, xsq0, 1);
    xsq0 += __shfl_xor_sync(0xffffffffu, xsq0, 2);
    xsq1 += __shfl_xor_sync(0xffffffffu, xsq1, 1);
    xsq1 += __shfl_xor_sync(0xffffffffu, xsq1, 2);

    float zero4[4] = {0.0f, 0.0f, 0.0f, 0.0f};
    float best0 = 3.4e38f, best1 = 3.4e38f;
    int idx0 = 0, idx1 = 0;

    for (int chunk = 0; chunk < NCHUNKS; chunk++) {
        if (chunk + 1 < NCHUNKS) { stage(chunk + 1); CP_WAIT(1); }
        else                     { CP_WAIT(0); }
        __syncthreads();

        const uint32_t bb = sbase + (uint32_t)((chunk & 1) * BUF_SZ);
        const char* ebase = smem + (chunk & 1) * BUF_SZ + ESQ_OFF;

        #pragma unroll
        for (int nb = 0; nb < CCHUNK / 8; nb++) {
            unsigned B0[8], B1[8];
            {
                uint32_t a = bb + (uint32_t)(nb * 8 * ROW_PITCH) + rowoff;
                LDSM_X4(B0, a);
                LDSM_X4(B0 + 4, a + 64);
                a += SPLIT_STRIDE;
                LDSM_X4(B1, a);
                LDSM_X4(B1 + 4, a + 64);
            }

            float cacc[4][4];
            #pragma unroll
            for (int kc = 0; kc < 4; kc++) {
                unsigned b00 = B0[2 * kc], b01 = B0[2 * kc + 1];
                unsigned b10 = B1[2 * kc], b11 = B1[2 * kc + 1];
                MMA16816(cacc[kc], A[0][kc], b00, b01, zero4);    // x0*e0
                MMA16816(cacc[kc], A[0][kc], b10, b11, cacc[kc]); // x0*e1
                MMA16816(cacc[kc], A[1][kc], b00, b01, cacc[kc]); // x1*e0
            }

            float2 eq = *(const float2*)(ebase + (nb * 8 + 2 * q) * 4);
            float k0 = ((cacc[0][0] + cacc[1][0]) + (cacc[2][0] + cacc[3][0])) + eq.x;
            float k1 = ((cacc[0][1] + cacc[1][1]) + (cacc[2][1] + cacc[3][1])) + eq.y;
            float k2 = ((cacc[0][2] + cacc[1][2]) + (cacc[2][2] + cacc[3][2])) + eq.x;
            float k3 = ((cacc[0][3] + cacc[1][3]) + (cacc[2][3] + cacc[3][3])) + eq.y;

            int col = chunk * CCHUNK + nb * 8 + 2 * q;
            if (k0 < best0) { best0 = k0; idx0 = col; }        // ascending: first-min
            if (k1 < best0) { best0 = k1; idx0 = col + 1; }
            if (k2 < best1) { best1 = k2; idx1 = col; }
            if (k3 < best1) { best1 = k3; idx1 = col + 1; }
        }
        __syncthreads();   // buffer (chunk&1) free for prefetch at chunk+1
    }

    // ---- combine across the 4 quad lanes (cols), tie -> lower index ----
    #pragma unroll
    for (int o = 1; o < 4; o <<= 1) {
        float ob = __shfl_xor_sync(0xffffffffu, best0, o);
        int   oi = __shfl_xor_sync(0xffffffffu, idx0,  o);
        if (ob < best0 || (ob == best0 && oi < idx0)) { best0 = ob; idx0 = oi; }
        ob = __shfl_xor_sync(0xffffffffu, best1, o);
        oi = __shfl_xor_sync(0xffffffffu, idx1,  o);
        if (ob < best1 || (ob == best1 && oi < idx1)) { best1 = ob; idx1 = oi; }
    }

    // ---- fused gather: all 4 quad lanes copy E[argmin] rows to Z ----
    {
        const float4* e0 = (const float4*)E + (size_t)idx0 * 16;
        const float4* e1 = (const float4*)E + (size_t)idx1 * 16;
        float4* z0 = out_z + (size_t)row0 * 16;
        float4* z1 = out_z + (size_t)row1 * 16;
        #pragma unroll
        for (int j = 0; j < 4; j++) {
            z0[q + 4 * j] = e0[q + 4 * j];
            z1[q + 4 * j] = e1[q + 4 * j];
        }
    }

    float lsum = 0.0f;
    if (q == 0) {
        float m0 = xsq0 + best0;
        float m1 = xsq1 + best1;
        out_arg[row0]  = (float)idx0;  out_arg[row1]  = (float)idx1;
        out_mind[row0] = m0;           out_mind[row1] = m1;
        atomicAdd(&g_counts[idx0], 1.0f);
        atomicAdd(&g_counts[idx1], 1.0f);
        lsum = m0 + m1;

        const float4* xr0 = (const float4*)(X + (size_t)row0 * DIM);
        const float4* xr1 = (const float4*)(X + (size_t)row1 * DIM);
        float* sp0 = &g_sums[(size_t)idx0 * DIM];
        float* sp1 = &g_sums[(size_t)idx1 * DIM];
        #pragma unroll
        for (int j = 0; j < 16; j++) {
            float4 v = xr0[j];
            asm volatile("red.global.add.v4.f32 [%0], {%1,%2,%3,%4};"
                         :: "l"(sp0 + 4 * j), "f"(v.x), "f"(v.y), "f"(v.z), "f"(v.w)
                         : "memory");
            v = xr1[j];
            asm volatile("red.global.add.v4.f32 [%0], {%1,%2,%3,%4};"
                         :: "l"(sp1 + 4 * j), "f"(v.x), "f"(v.y), "f"(v.z), "f"(v.w)
                         : "memory");
        }
    }

    float* sred = (float*)(smem + SM_RED);
    __syncthreads();
    sred[tid] = lsum;
    __syncthreads();
    for (int s = 128; s > 0; s >>= 1) {
        if (tid < s) sred[tid] += sred[tid + s];
        __syncthreads();
    }
    if (tid == 0) atomicAdd(&g_loss, sred[0]);
}

// ---------------------------------------------------------------------------
// cs + loss
// ---------------------------------------------------------------------------
__global__ void cs_kernel(const float* __restrict__ cluster_sizes,
                          float* __restrict__ out_loss, float* __restrict__ out_cs) {
    __shared__ float warp_sums[32];
    int k = threadIdx.x;
    float cs_pre = GAMMA_F * cluster_sizes[k] + ONE_M_GAMMA * g_counts[k];
    float v = cs_pre;
    #pragma unroll
    for (int o = 16; o > 0; o >>= 1) v += __shfl_xor_sync(0xffffffffu, v, o);
    if ((k & 31) == 0) warp_sums[k >> 5] = v;
    __syncthreads();
    if (k < 32) {
        float w = warp_sums[k];
        #pragma unroll
        for (int o = 16; o > 0; o >>= 1) w += __shfl_xor_sync(0xffffffffu, w, o);
        if (k == 0) warp_sums[0] = w;
    }
    __syncthreads();
    float total = warp_sums[0];
    float denom = 1.0f + ALPHA_F * (float)K_CODES / total;
    float cs = (cs_pre + ALPHA_F) / denom;
    out_cs[k]   = cs;
    g_cs_inv[k] = 1.0f / cs;
    if (k == 0) out_loss[0] = BETA_F * g_loss / (float)N_PTS;
}

// ---------------------------------------------------------------------------
// ma + E_new
// ---------------------------------------------------------------------------
__global__ void ema_kernel(const float* __restrict__ moving_avg,
                           float* __restrict__ out_enew, float* __restrict__ out_ma) {
    int i = blockIdx.x * 256 + threadIdx.x;
    int k = i >> 6;
    float ma = GAMMA_F * moving_avg[i] + ONE_M_GAMMA * g_sums[i];
    out_ma[i]   = ma;
    out_enew[i] = ma * g_cs_inv[k];
}

// ---------------------------------------------------------------------------
// launch
// ---------------------------------------------------------------------------
extern "C" void kernel_launch(void* const* d_in, const int* in_sizes, int n_in,
                              void* d_out, int out_size) {
    const float* X    = (const float*)d_in[0];
    const float* E    = (const float*)d_in[1];
    const float* cssz = (const float*)d_in[2];
    const float* mavg = (const float*)d_in[3];

    float* out = (float*)d_out;
    float* out_z    = out;
    float* out_loss = out + (size_t)N_PTS * DIM;
    float* out_arg  = out_loss + 1;
    float* out_mind = out_arg + N_PTS;
    float* out_enew = out_mind + N_PTS;
    float* out_cs   = out_enew + K_CODES * DIM;
    float* out_ma   = out_cs + K_CODES;

    static bool attr_done = false;
    if (!attr_done) {
        cudaFuncSetAttribute(dist_kernel,
                             cudaFuncAttributeMaxDynamicSharedMemorySize, SM_TOTAL);
        attr_done = true;
    }

    prep_E<<<(K_CODES * DIM) / 256, 256>>>(E);
    dist_kernel<<<N_PTS / 128, 256, SM_TOTAL>>>(X, E, (float4*)out_z,
                                                out_arg, out_mind);
    cs_kernel<<<1, 1024>>>(cssz, out_loss, out_cs);
    ema_kernel<<<(K_CODES * DIM) / 256, 256>>>(mavg, out_enew, out_ma);
}

// round 11
// speedup vs baseline: 5.3850x; 1.2085x over previous
#include <cuda_runtime.h>
#include <cuda_bf16.h>
#include <cuda_fp16.h>
#include <cstdint>

#define K_CODES 1024
#define DIM 64
#define N_PTS 131072
#define GAMMA_F 0.99f
#define ONE_M_GAMMA 0.01f
#define ALPHA_F 1e-9f
#define BETA_F 0.25f

#define CCHUNK 64               // codes per smem chunk (double-buffered)
#define ROW_PITCH 144           // bytes per code row in smem (64*2 + 16 pad)
#define SPLIT_STRIDE (CCHUNK * ROW_PITCH)        // 9216
#define ESQ_OFF (2 * SPLIT_STRIDE)               // 18432
#define BUF_SZ (ESQ_OFF + CCHUNK * 4)            // 18688
#define SM_RED (2 * BUF_SZ)                      // 37376
#define SM_TOTAL (SM_RED + 128 * 4)              // 37888
#define NCHUNKS (K_CODES / CCHUNK)               // 16

// ---- scratch (__device__ globals; no allocs) ----
__device__ __align__(16) __half g_Es0[K_CODES * DIM];
__device__ __align__(16) __half g_Es1[K_CODES * DIM];
__device__ __align__(16) float g_esq[K_CODES];
__device__ float g_counts[K_CODES];
__device__ float g_sums[K_CODES * DIM];
__device__ float g_loss;
__device__ float g_cs_inv[K_CODES];

// mma.sync m16n8k16 fp16 -> f32 (sm_80+ baseline; valid at compute_103)
#define MMA16816(d, a, b0v, b1v, c)                                          \
    asm volatile("mma.sync.aligned.m16n8k16.row.col.f32.f16.f16.f32 "        \
        "{%0,%1,%2,%3}, {%4,%5,%6,%7}, {%8,%9}, {%10,%11,%12,%13};"          \
        : "=f"((d)[0]), "=f"((d)[1]), "=f"((d)[2]), "=f"((d)[3])             \
        : "r"((a)[0]), "r"((a)[1]), "r"((a)[2]), "r"((a)[3]),                \
          "r"(b0v), "r"(b1v),                                                \
          "f"((c)[0]), "f"((c)[1]), "f"((c)[2]), "f"((c)[3]))

#define LDSM_X4(r, addr)                                                     \
    asm volatile("ldmatrix.sync.aligned.m8n8.x4.shared.b16 {%0,%1,%2,%3}, [%4];" \
        : "=r"((r)[0]), "=r"((r)[1]), "=r"((r)[2]), "=r"((r)[3])             \
        : "r"(addr))

#define CP_ASYNC16(dst, src)                                                 \
    asm volatile("cp.async.cg.shared.global [%0], [%1], 16;"                 \
        :: "r"(dst), "l"(src))
#define CP_COMMIT()  asm volatile("cp.async.commit_group;" ::: "memory")
#define CP_WAIT(n)   asm volatile("cp.async.wait_group %0;" :: "n"(n) : "memory")

__device__ __forceinline__ uint32_t smem_u32(const void* p) {
    uint32_t a;
    asm("{ .reg .u64 t; cvta.to.shared.u64 t, %1; cvt.u32.u64 %0, t; }"
        : "=r"(a) : "l"(p));
    return a;
}
__device__ __forceinline__ unsigned pack_h2(__half lo, __half hi) {
    __half2 v = __halves2half2(lo, hi);
    return *(unsigned*)&v;
}

// ---------------------------------------------------------------------------
// prep_E: 2-term fp16 splits of e + esq, + zero stats.  grid = K*DIM/256.
// ---------------------------------------------------------------------------
__global__ void prep_E(const float* __restrict__ E) {
    __shared__ float ws[8];
    int e = blockIdx.x * 256 + threadIdx.x;
    float v = E[e];

    __half h0 = __float2half(v);
    float r1 = v - __half2float(h0);
    __half h1 = __float2half(r1);
    g_Es0[e] = h0; g_Es1[e] = h1;

    g_sums[e] = 0.0f;
    if (e < K_CODES) g_counts[e] = 0.0f;
    if (e == 0) g_loss = 0.0f;

    float sq = v * v;
    #pragma unroll
    for (int o = 16; o > 0; o >>= 1) sq += __shfl_xor_sync(0xffffffffu, sq, o);
    if ((threadIdx.x & 31) == 0) ws[threadIdx.x >> 5] = sq;
    __syncthreads();
    if ((threadIdx.x & 63) == 0) {
        int g = threadIdx.x >> 6;
        g_esq[e >> 6] = ws[2 * g] + ws[2 * g + 1];
    }
}

// ---------------------------------------------------------------------------
// dist kernel: HMMA fp16 2-split (3 products), 32 rows per warp (2 M-tiles),
// key = esq - 2*x.e, argmin + stats + fused gather.
// 128 threads = 4 warps x 32 points = 128 points/CTA. grid = N/128.
// ---------------------------------------------------------------------------
__global__ void __launch_bounds__(128, 3)
dist_kernel(const float* __restrict__ X, const float* __restrict__ E,
            float4* __restrict__ out_z,
            float* __restrict__ out_arg, float* __restrict__ out_mind) {
    extern __shared__ char smem[];
    const uint32_t sbase = smem_u32(smem);
    const int tid = threadIdx.x;
    const int wid = tid >> 5;
    const int lane = tid & 31;
    const int g = lane >> 2;          // 0..7
    const int q = lane & 3;           // 0..3
    const int tileRow = blockIdx.x * 128 + wid * 32;

    // per-lane ldmatrix row offset (tile t = lane>>3, row r = lane&7)
    const int lt = lane >> 3;
    const int lr = lane & 7;
    const uint32_t rowoff = (uint32_t)(lr * ROW_PITCH + (lt >> 1) * 32 + (lt & 1) * 16);

    // ---- kick off chunk-0 B staging before doing A-split math ----
    const __half* es[2] = {g_Es0, g_Es1};
    auto stage = [&](int chunk) {
        uint32_t bb = sbase + (uint32_t)((chunk & 1) * BUF_SZ);
        #pragma unroll
        for (int ii = 0; ii < 8; ii++) {
            int i = tid + ii * 128;       // 0..1023 = 2 splits x 512 uint4
            int s = i >> 9;
            int r = i & 511;
            int n = r >> 3, c = r & 7;
            CP_ASYNC16(bb + s * SPLIT_STRIDE + n * ROW_PITCH + c * 16,
                       es[s] + (size_t)chunk * CCHUNK * DIM + r * 8);
        }
        if (tid < CCHUNK / 4)
            CP_ASYNC16(bb + ESQ_OFF + tid * 16, g_esq + chunk * CCHUNK + tid * 4);
        CP_COMMIT();
    };
    stage(0);

    // ---- A fragments in-register from X (2-way fp16 split of -2x), 2 tiles --
    unsigned A[2][2][4][4];        // [tile][split][kc][reg]
    float xsq[2][2];               // [tile][half: row g / row g+8]
    #pragma unroll
    for (int t = 0; t < 2; t++) {
        const int r0 = tileRow + t * 16 + g;
        const int r1 = r0 + 8;
        float s0 = 0.0f, s1 = 0.0f;
        #pragma unroll
        for (int kc = 0; kc < 4; kc++) {
            float2 v00 = *(const float2*)(X + (size_t)r0 * DIM + kc * 16 + q * 2);
            float2 v01 = *(const float2*)(X + (size_t)r0 * DIM + kc * 16 + q * 2 + 8);
            float2 v10 = *(const float2*)(X + (size_t)r1 * DIM + kc * 16 + q * 2);
            float2 v11 = *(const float2*)(X + (size_t)r1 * DIM + kc * 16 + q * 2 + 8);
            s0 += v00.x * v00.x + v00.y * v00.y + v01.x * v01.x + v01.y * v01.y;
            s1 += v10.x * v10.x + v10.y * v10.y + v11.x * v11.x + v11.y * v11.y;

            const float2 vs[4] = {v00, v10, v01, v11};
            #pragma unroll
            for (int j = 0; j < 4; j++) {
                float ax = -2.0f * vs[j].x, ay = -2.0f * vs[j].y;
                __half x0 = __float2half(ax);
                __half x1 = __float2half(ax - __half2float(x0));
                __half y0 = __float2half(ay);
                __half y1 = __float2half(ay - __half2float(y0));
                A[t][0][kc][j] = pack_h2(x0, y0);
                A[t][1][kc][j] = pack_h2(x1, y1);
            }
        }
        // quad-lane reduce (4 lanes hold disjoint 16-col subsets)
        s0 += __shfl_xor_sync(0xffffffffu, s0, 1);
        s0 += __shfl_xor_sync(0xffffffffu, s0, 2);
        s1 += __shfl_xor_sync(0xffffffffu, s1, 1);
        s1 += __shfl_xor_sync(0xffffffffu, s1, 2);
        xsq[t][0] = s0;
        xsq[t][1] = s1;
    }

    float zero4[4] = {0.0f, 0.0f, 0.0f, 0.0f};
    float best[2][2] = {{3.4e38f, 3.4e38f}, {3.4e38f, 3.4e38f}};
    int   bidx[2][2] = {{0, 0}, {0, 0}};

    for (int chunk = 0; chunk < NCHUNKS; chunk++) {
        if (chunk + 1 < NCHUNKS) { stage(chunk + 1); CP_WAIT(1); }
        else                     { CP_WAIT(0); }
        __syncthreads();

        const uint32_t bb = sbase + (uint32_t)((chunk & 1) * BUF_SZ);
        const char* ebase = smem + (chunk & 1) * BUF_SZ + ESQ_OFF;

        #pragma unroll
        for (int nb = 0; nb < CCHUNK / 8; nb++) {
            unsigned B0[8], B1[8];
            {
                uint32_t a = bb + (uint32_t)(nb * 8 * ROW_PITCH) + rowoff;
                LDSM_X4(B0, a);
                LDSM_X4(B0 + 4, a + 64);
                a += SPLIT_STRIDE;
                LDSM_X4(B1, a);
                LDSM_X4(B1 + 4, a + 64);
            }

            // 6 independent kc-chains: [tile][product]
            float acc[2][3][4];
            #pragma unroll
            for (int kc = 0; kc < 4; kc++) {
                unsigned b00 = B0[2 * kc], b01 = B0[2 * kc + 1];
                unsigned b10 = B1[2 * kc], b11 = B1[2 * kc + 1];
                #pragma unroll
                for (int t = 0; t < 2; t++) {
                    MMA16816(acc[t][0], A[t][0][kc], b00, b01,
                             kc == 0 ? zero4 : acc[t][0]);   // x0*e0
                    MMA16816(acc[t][1], A[t][0][kc], b10, b11,
                             kc == 0 ? zero4 : acc[t][1]);   // x0*e1
                    MMA16816(acc[t][2], A[t][1][kc], b00, b01,
                             kc == 0 ? zero4 : acc[t][2]);   // x1*e0
                }
            }

            float2 eq = *(const float2*)(ebase + (nb * 8 + 2 * q) * 4);
            int col = chunk * CCHUNK + nb * 8 + 2 * q;
            #pragma unroll
            for (int t = 0; t < 2; t++) {
                float k0 = (acc[t][0][0] + acc[t][1][0]) + (acc[t][2][0] + eq.x);
                float k1 = (acc[t][0][1] + acc[t][1][1]) + (acc[t][2][1] + eq.y);
                float k2 = (acc[t][0][2] + acc[t][1][2]) + (acc[t][2][2] + eq.x);
                float k3 = (acc[t][0][3] + acc[t][1][3]) + (acc[t][2][3] + eq.y);
                if (k0 < best[t][0]) { best[t][0] = k0; bidx[t][0] = col; }
                if (k1 < best[t][0]) { best[t][0] = k1; bidx[t][0] = col + 1; }
                if (k2 < best[t][1]) { best[t][1] = k2; bidx[t][1] = col; }
                if (k3 < best[t][1]) { best[t][1] = k3; bidx[t][1] = col + 1; }
            }
        }
        __syncthreads();   // buffer (chunk&1) free for prefetch at chunk+1
    }

    // ---- combine across the 4 quad lanes (cols), tie -> lower index ----
    #pragma unroll
    for (int t = 0; t < 2; t++) {
        #pragma unroll
        for (int h = 0; h < 2; h++) {
            #pragma unroll
            for (int o = 1; o < 4; o <<= 1) {
                float ob = __shfl_xor_sync(0xffffffffu, best[t][h], o);
                int   oi = __shfl_xor_sync(0xffffffffu, bidx[t][h], o);
                if (ob < best[t][h] || (ob == best[t][h] && oi < bidx[t][h])) {
                    best[t][h] = ob; bidx[t][h] = oi;
                }
            }
        }
    }

    // ---- fused gather + outputs + stats for 4 rows per thread-group ----
    float lsum = 0.0f;
    #pragma unroll
    for (int t = 0; t < 2; t++) {
        #pragma unroll
        for (int h = 0; h < 2; h++) {
            const int row = tileRow + t * 16 + h * 8 + g;
            const int id  = bidx[t][h];
            // gather: all 4 quad lanes copy E[id] row to Z
            const float4* ee = (const float4*)E + (size_t)id * 16;
            float4* zz = out_z + (size_t)row * 16;
            #pragma unroll
            for (int j = 0; j < 4; j++) zz[q + 4 * j] = ee[q + 4 * j];

            if (q == 0) {
                float m = xsq[t][h] + best[t][h];
                out_arg[row]  = (float)id;
                out_mind[row] = m;
                atomicAdd(&g_counts[id], 1.0f);
                lsum += m;
                const float4* xr = (const float4*)(X + (size_t)row * DIM);
                float* sp = &g_sums[(size_t)id * DIM];
                #pragma unroll
                for (int j = 0; j < 16; j++) {
                    float4 v = xr[j];
                    asm volatile("red.global.add.v4.f32 [%0], {%1,%2,%3,%4};"
                                 :: "l"(sp + 4 * j),
                                    "f"(v.x), "f"(v.y), "f"(v.z), "f"(v.w)
                                 : "memory");
                }
            }
        }
    }

    float* sred = (float*)(smem + SM_RED);
    __syncthreads();
    sred[tid] = lsum;
    __syncthreads();
    for (int s = 64; s > 0; s >>= 1) {
        if (tid < s) sred[tid] += sred[tid + s];
        __syncthreads();
    }
    if (tid == 0) atomicAdd(&g_loss, sred[0]);
}

// ---------------------------------------------------------------------------
// cs + loss
// ---------------------------------------------------------------------------
__global__ void cs_kernel(const float* __restrict__ cluster_sizes,
                          float* __restrict__ out_loss, float* __restrict__ out_cs) {
    __shared__ float warp_sums[32];
    int k = threadIdx.x;
    float cs_pre = GAMMA_F * cluster_sizes[k] + ONE_M_GAMMA * g_counts[k];
    float v = cs_pre;
    #pragma unroll
    for (int o = 16; o > 0; o >>= 1) v += __shfl_xor_sync(0xffffffffu, v, o);
    if ((k & 31) == 0) warp_sums[k >> 5] = v;
    __syncthreads();
    if (k < 32) {
        float w = warp_sums[k];
        #pragma unroll
        for (int o = 16; o > 0; o >>= 1) w += __shfl_xor_sync(0xffffffffu, w, o);
        if (k == 0) warp_sums[0] = w;
    }
    __syncthreads();
    float total = warp_sums[0];
    float denom = 1.0f + ALPHA_F * (float)K_CODES / total;
    float cs = (cs_pre + ALPHA_F) / denom;
    out_cs[k]   = cs;
    g_cs_inv[k] = 1.0f / cs;
    if (k == 0) out_loss[0] = BETA_F * g_loss / (float)N_PTS;
}

// ---------------------------------------------------------------------------
// ma + E_new
// ---------------------------------------------------------------------------
__global__ void ema_kernel(const float* __restrict__ moving_avg,
                           float* __restrict__ out_enew, float* __restrict__ out_ma) {
    int i = blockIdx.x * 256 + threadIdx.x;
    int k = i >> 6;
    float ma = GAMMA_F * moving_avg[i] + ONE_M_GAMMA * g_sums[i];
    out_ma[i]   = ma;
    out_enew[i] = ma * g_cs_inv[k];
}

// ---------------------------------------------------------------------------
// launch
// ---------------------------------------------------------------------------
extern "C" void kernel_launch(void* const* d_in, const int* in_sizes, int n_in,
                              void* d_out, int out_size) {
    const float* X    = (const float*)d_in[0];
    const float* E    = (const float*)d_in[1];
    const float* cssz = (const float*)d_in[2];
    const float* mavg = (const float*)d_in[3];

    float* out = (float*)d_out;
    float* out_z    = out;
    float* out_loss = out + (size_t)N_PTS * DIM;
    float* out_arg  = out_loss + 1;
    float* out_mind = out_arg + N_PTS;
    float* out_enew = out_mind + N_PTS;
    float* out_cs   = out_enew + K_CODES * DIM;
    float* out_ma   = out_cs + K_CODES;

    static bool attr_done = false;
    if (!attr_done) {
        cudaFuncSetAttribute(dist_kernel,
                             cudaFuncAttributeMaxDynamicSharedMemorySize, SM_TOTAL);
        attr_done = true;
    }

    prep_E<<<(K_CODES * DIM) / 256, 256>>>(E);
    dist_kernel<<<N_PTS / 128, 128, SM_TOTAL>>>(X, E, (float4*)out_z,
                                                out_arg, out_mind);
    cs_kernel<<<1, 1024>>>(cssz, out_loss, out_cs);
    ema_kernel<<<(K_CODES * DIM) / 256, 256>>>(mavg, out_enew, out_ma);
}